// round 6
// baseline (speedup 1.0000x reference)
#include <cuda_runtime.h>
#include <cuda_bf16.h>
#include <math.h>
#include <stdint.h>

// ---------------- problem constants ----------------
#define V_ 50257
#define VP_ 50432            // V padded to multiple of 256
#define D_ 384
#define T_ 300
#define B_ 16
#define H_ 16
#define DH_ 24
#define L_ 8
#define FF_ 1536
#define BT_ (B_ * T_)        // 4800
#define MP_ 4864             // BT padded to multiple of 128

// tcgen05 only exists in the arch-specific (sm_103a) compilation pass.
#if defined(__CUDA_ARCH__) && (__CUDA_ARCH__ == 1030) && \
    (defined(__CUDA_ARCH_FEAT_SM103_ALL) || defined(__CUDA_ARCH_SPECIFIC__) || defined(__CUDA_ARCH_FAMILY_SPECIFIC__))
#define TCGEN_OK 1
#else
#define TCGEN_OK 0
#endif

// ---------------- scratch (device globals; no allocation allowed) ---------
__device__ float g_x[BT_ * D_];
__device__ float g_qkv[BT_ * 3 * D_];
__device__ float g_y[BT_ * D_];
__device__ float g_rowloss[BT_];

// activation bf16 planes (padded rows stay zero)
__device__ __nv_bfloat16 g_xh[MP_ * D_],  g_xl[MP_ * D_];
__device__ __nv_bfloat16 g_oh[MP_ * D_],  g_ol[MP_ * D_];
__device__ __nv_bfloat16 g_hh[MP_ * FF_], g_hl[MP_ * FF_];

// TRANSPOSED weight bf16 planes: [N, K] layout (tcgen05 SS: D = A @ B^T)
__device__ __nv_bfloat16 g_wqkv_h[L_ * 3 * D_ * D_], g_wqkv_l[L_ * 3 * D_ * D_];
__device__ __nv_bfloat16 g_wo_h[L_ * D_ * D_],       g_wo_l[L_ * D_ * D_];
__device__ __nv_bfloat16 g_w1_h[L_ * FF_ * D_],      g_w1_l[L_ * FF_ * D_];
__device__ __nv_bfloat16 g_w2_h[L_ * D_ * FF_],      g_w2_l[L_ * D_ * FF_];
__device__ __nv_bfloat16 g_wout_h[VP_ * D_],         g_wout_l[VP_ * D_];

__device__ __forceinline__ void bf16_split(float x, __nv_bfloat16& h, __nv_bfloat16& l) {
    h = __float2bfloat16_rn(x);
    l = __float2bfloat16_rn(x - __bfloat162float(h));
}

// ---------------- PTX helpers ----------------
__device__ __forceinline__ uint32_t smem_u32(const void* p) {
    return (uint32_t)__cvta_generic_to_shared(p);
}

#if TCGEN_OK
__device__ __forceinline__ uint32_t elect1() {
    uint32_t pred;
    asm volatile("{\n\t.reg .pred p;\n\telect.sync _|p, 0xFFFFFFFF;\n\tselp.b32 %0, 1, 0, p;\n\t}"
                 : "=r"(pred));
    return pred;
}
#define TC_ALLOC(sa, n) \
    asm volatile("tcgen05.alloc.cta_group::1.sync.aligned.shared::cta.b32 [%0], %1;" \
                 :: "r"(sa), "r"((uint32_t)(n)) : "memory")
#define TC_RELINQ() \
    asm volatile("tcgen05.relinquish_alloc_permit.cta_group::1.sync.aligned;")
#define TC_DEALLOC(t, n) \
    asm volatile("tcgen05.dealloc.cta_group::1.sync.aligned.b32 %0, %1;" \
                 :: "r"(t), "r"((uint32_t)(n)))
#define TC_COMMIT(mb) \
    asm volatile("tcgen05.commit.cta_group::1.mbarrier::arrive::one.shared::cluster.b64 [%0];" \
                 :: "r"(mb) : "memory")
#define TC_FENCE_AFTER() asm volatile("tcgen05.fence::after_thread_sync;" ::: "memory")
#define FENCE_ASYNC() asm volatile("fence.proxy.async.shared::cta;" ::: "memory")
#define TC_WAIT_LD() asm volatile("tcgen05.wait::ld.sync.aligned;" ::: "memory")
#define MB_INIT(addr, cnt) \
    asm volatile("mbarrier.init.shared.b64 [%0], %1;" :: "r"(addr), "r"((uint32_t)(cnt)) : "memory")
#define MB_INVAL(addr) \
    asm volatile("mbarrier.inval.shared.b64 [%0];" :: "r"(addr) : "memory")
#define MB_WAIT(addr, phase) do {                                                    \
    uint32_t _done;                                                                  \
    asm volatile("{\n\t.reg .pred p;\n\t"                                            \
        "mbarrier.try_wait.parity.acquire.cta.shared::cta.b64 p, [%1], %2;\n\t"      \
        "selp.b32 %0, 1, 0, p;\n\t}"                                                 \
        : "=r"(_done) : "r"(addr), "r"((uint32_t)(phase)) : "memory");               \
    while (!_done) {                                                                 \
        asm volatile("{\n\t.reg .pred p;\n\t"                                        \
            "mbarrier.try_wait.parity.acquire.cta.shared::cta.b64 p, [%1], %2, 0x989680;\n\t" \
            "selp.b32 %0, 1, 0, p;\n\t}"                                             \
            : "=r"(_done) : "r"(addr), "r"((uint32_t)(phase)) : "memory");           \
    } } while (0)

#define TC_LD32(r, addr) \
    asm volatile("tcgen05.ld.sync.aligned.32x32b.x32.b32 " \
        "{%0, %1, %2, %3, %4, %5, %6, %7, %8, %9, %10, %11, %12, %13, %14, %15, " \
        " %16, %17, %18, %19, %20, %21, %22, %23, %24, %25, %26, %27, %28, %29, %30, %31}, [%32];" \
        : "=r"((r)[0]), "=r"((r)[1]), "=r"((r)[2]), "=r"((r)[3]), \
          "=r"((r)[4]), "=r"((r)[5]), "=r"((r)[6]), "=r"((r)[7]), \
          "=r"((r)[8]), "=r"((r)[9]), "=r"((r)[10]), "=r"((r)[11]), \
          "=r"((r)[12]), "=r"((r)[13]), "=r"((r)[14]), "=r"((r)[15]), \
          "=r"((r)[16]), "=r"((r)[17]), "=r"((r)[18]), "=r"((r)[19]), \
          "=r"((r)[20]), "=r"((r)[21]), "=r"((r)[22]), "=r"((r)[23]), \
          "=r"((r)[24]), "=r"((r)[25]), "=r"((r)[26]), "=r"((r)[27]), \
          "=r"((r)[28]), "=r"((r)[29]), "=r"((r)[30]), "=r"((r)[31]) \
        : "r"(addr))

// SS bf16 mma: D[128,128] += A @ B^T  (A,B smem descriptors, SW128)
__device__ __forceinline__ void mma_ss(uint32_t d, uint64_t a, uint64_t b, uint32_t idesc, bool acc) {
    uint32_t en = acc ? 1u : 0u;
    asm volatile("{\n\t.reg .pred p;\n\tsetp.ne.u32 p, %5, 0;\n\t"
        "tcgen05.mma.cta_group::1.kind::f16 [%0], %1, %2, %3, {%4,%4,%4,%4}, p;\n\t}"
        :: "r"(d), "l"(a), "l"(b), "r"(idesc), "r"(0u), "r"(en) : "memory");
}
#endif // TCGEN_OK

// idesc: dtype=F32, atype=btype=BF16, N=128, M=128 (matches 0x490-style encoding)
#define IDESC_128 ((1u << 4) | (1u << 7) | (1u << 10) | ((128u / 8u) << 17) | ((128u / 16u) << 24))
// SW128 K-major smem descriptor base (LBO=1, SBO=64, version=1, layout=SW128)
#define DESC_BASE ((2ull << 61) | (1ull << 46) | (64ull << 32) | (1ull << 16))

// ==================== GEMM: tcgen05 bf16x3 (specific) / fp32 fallback ====
// C[M,N] = A[M,K] @ W[K,N] (+bias, relu). A as bf16 hi/lo planes [Mpad,K];
// W as TRANSPOSED hi/lo planes [Npad,K]. NT = number of 128-col B tiles.
template <int NT>
__global__ __launch_bounds__(256)
void gemm_tc(const __nv_bfloat16* __restrict__ Ahg, const __nv_bfloat16* __restrict__ Alg,
             const __nv_bfloat16* __restrict__ Bhg, const __nv_bfloat16* __restrict__ Blg,
             const float* __restrict__ bias, float* __restrict__ Cf,
             __nv_bfloat16* __restrict__ Ch, __nv_bfloat16* __restrict__ Cl,
             int M, int N, int K, int relu) {
    extern __shared__ char dyn[];
    const int tid  = threadIdx.x;
#if TCGEN_OK
    constexpr int NBUF  = 2 + 2 * NT;     // Ah, Al, {Bh, Bl} x NT
    constexpr int BUFB  = 16384;          // 128 rows x 64 bf16 (SW128)
    constexpr int STAGE = NBUF * BUFB;
    char* sb = (char*)(((uintptr_t)dyn + 1023) & ~(uintptr_t)1023);
    __shared__ uint32_t s_tm[1];
    __shared__ __align__(8) uint64_t s_mb[2];

    const int warp = tid >> 5;
    const int lane = tid & 31;
    const int bm = blockIdx.y * 128;
    const int bn = blockIdx.x * (NT * 128);

    if (warp == 0) { TC_ALLOC(smem_u32(s_tm), 512); TC_RELINQ(); }
    if (tid == 0) { MB_INIT(smem_u32(&s_mb[0]), 1); MB_INIT(smem_u32(&s_mb[1]), 1); }
    __syncthreads();
    const uint32_t tmem = s_tm[0];
    const uint32_t mb0 = smem_u32(&s_mb[0]);
    const uint32_t mb1 = smem_u32(&s_mb[1]);

    const int nst = K >> 6;   // K stages of 64

    auto load_stage = [&](int st, int k0) {
        char* s = sb + st * STAGE;
        for (int i = tid; i < NBUF * 1024; i += 256) {
            int buf = i >> 10, ch = i & 1023;
            int row = ch >> 3, c16 = ch & 7;
            const __nv_bfloat16* src;
            if (buf == 0)      src = Ahg + (size_t)(bm + row) * K + k0 + c16 * 8;
            else if (buf == 1) src = Alg + (size_t)(bm + row) * K + k0 + c16 * 8;
            else {
                int j = (buf - 2) >> 1;
                const __nv_bfloat16* P = ((buf - 2) & 1) ? Blg : Bhg;
                src = P + (size_t)(bn + j * 128 + row) * K + k0 + c16 * 8;
            }
            uint32_t off = row * 128 + c16 * 16;
            uint32_t sw = off ^ ((off >> 3) & 0x70);
            *(uint4*)(s + buf * BUFB + sw) = *(const uint4*)src;
        }
    };

    load_stage(0, 0);
    if (nst > 1) load_stage(1, 64);

    int ph0 = 0, ph1 = 0;
    for (int st = 0; st < nst; st++) {
        int b = st & 1;
        FENCE_ASYNC();
        __syncthreads();
        if (warp == 0 && elect1()) {
            char* s = sb + b * STAGE;
            uint64_t ah = DESC_BASE | ((smem_u32(s) >> 4) & 0x3FFF);
            uint64_t al = DESC_BASE | ((smem_u32(s + BUFB) >> 4) & 0x3FFF);
#pragma unroll
            for (int j = 0; j < NT; j++) {
                uint64_t bh = DESC_BASE | ((smem_u32(s + (2 + 2 * j) * BUFB) >> 4) & 0x3FFF);
                uint64_t bl = DESC_BASE | ((smem_u32(s + (3 + 2 * j) * BUFB) >> 4) & 0x3FFF);
                uint32_t dst = tmem + j * 128;
#pragma unroll
                for (int k = 0; k < 4; k++) {
                    bool first = (st == 0) && (k == 0);
                    mma_ss(dst, ah + k * 2, bh + k * 2, IDESC_128, !first);
                    mma_ss(dst, ah + k * 2, bl + k * 2, IDESC_128, true);
                    mma_ss(dst, al + k * 2, bh + k * 2, IDESC_128, true);
                }
            }
            TC_COMMIT(b ? mb1 : mb0);
        }
        if (st + 2 < nst) {
            if (b == 0) { MB_WAIT(mb0, ph0); ph0 ^= 1; }
            else        { MB_WAIT(mb1, ph1); ph1 ^= 1; }
            load_stage(b, (st + 2) << 6);
        }
    }
    {
        int b = (nst - 1) & 1;
        if (b == 0) { MB_WAIT(mb0, ph0); }
        else        { MB_WAIT(mb1, ph1); }
    }
    TC_FENCE_AFTER();
    __syncthreads();

    // ---- epilogue: TMEM -> (smem transpose) -> gmem, coalesced
    const int sub = warp & 3;          // TMEM subpartition (rows 32*sub..)
    const int wg  = warp >> 2;         // column half
    const int NCH = NT * 64;           // cols per warpgroup
    float* smf = (float*)sb;           // reuse stage smem: 2 regions of 128x33 fp32
    for (int chk = 0; chk < NCH / 32; chk++) {
        uint32_t regs[32];
        int coll = wg * NCH + chk * 32;            // local col base
        TC_LD32(regs, tmem + coll);
        TC_WAIT_LD();
        int rl = sub * 32 + lane;
        float* dstp = smf + wg * (128 * 33) + rl * 33;
#pragma unroll
        for (int c = 0; c < 32; c++) {
            float v = __uint_as_float(regs[c]);
            int col = bn + coll + c;
            if (bias && col < N) v += bias[col];
            if (relu) v = fmaxf(v, 0.0f);
            dstp[c] = v;
        }
        __syncthreads();
        for (int e = tid; e < 128 * 64; e += 256) {
            int row = e >> 6;
            int cc  = e & 63;
            int gq  = cc >> 5;
            int c   = cc & 31;
            int col = bn + gq * NCH + chk * 32 + c;
            int grow = bm + row;
            float v = smf[gq * (128 * 33) + row * 33 + c];
            if (Cf) {
                if (grow < M && col < N) Cf[(size_t)grow * N + col] = v;
            } else {
                __nv_bfloat16 h, l;
                bf16_split(v, h, l);
                Ch[(size_t)grow * N + col] = h;
                Cl[(size_t)grow * N + col] = l;
            }
        }
        __syncthreads();
    }

    if (tid == 0) { MB_INVAL(mb0); MB_INVAL(mb1); }
    __syncthreads();
    if (warp == 0) TC_DEALLOC(tmem, 512);
#else
    // ---------- portable fp32 fallback (runs only if generic cubin loads) ----
    float* As = (float*)dyn;           // [8][128]
    float* Bs = As + 8 * 128;          // [8][128]
    const int bm = blockIdx.y * 128;
    const int tx = tid % 16;
    const int ty = tid / 16;

    for (int jt = 0; jt < NT; jt++) {
        const int bn = blockIdx.x * (NT * 128) + jt * 128;
        float acc[8][8];
#pragma unroll
        for (int i = 0; i < 8; i++)
#pragma unroll
            for (int j = 0; j < 8; j++) acc[i][j] = 0.0f;

        const int a_row  = tid >> 1;
        const int a_col4 = (tid & 1) * 4;
        const int b_row  = tid >> 5;
        const int b_col  = (tid & 31) * 4;

        for (int k0 = 0; k0 < K; k0 += 8) {
#pragma unroll
            for (int u = 0; u < 4; u++) {
                int kk = k0 + a_col4 + u;
                size_t ia = (size_t)(bm + a_row) * K + kk;
                As[(a_col4 + u) * 128 + a_row] =
                    __bfloat162float(Ahg[ia]) + __bfloat162float(Alg[ia]);
            }
#pragma unroll
            for (int u = 0; u < 4; u++) {
                int col = bn + b_col + u;
                size_t ib = (size_t)col * K + k0 + b_row;
                Bs[b_row * 128 + b_col + u] =
                    __bfloat162float(Bhg[ib]) + __bfloat162float(Blg[ib]);
            }
            __syncthreads();
#pragma unroll
            for (int kk = 0; kk < 8; kk++) {
                float a[8], bb[8];
#pragma unroll
                for (int i = 0; i < 8; i++) a[i] = As[kk * 128 + ty * 8 + i];
#pragma unroll
                for (int j = 0; j < 8; j++) bb[j] = Bs[kk * 128 + tx * 8 + j];
#pragma unroll
                for (int i = 0; i < 8; i++)
#pragma unroll
                    for (int j = 0; j < 8; j++) acc[i][j] += a[i] * bb[j];
            }
            __syncthreads();
        }

#pragma unroll
        for (int i = 0; i < 8; i++) {
            int row = bm + ty * 8 + i;
#pragma unroll
            for (int j = 0; j < 8; j++) {
                int col = bn + tx * 8 + j;
                float v = acc[i][j];
                if (bias && col < N) v += bias[col];
                if (relu) v = fmaxf(v, 0.0f);
                if (Cf) {
                    if (row < M && col < N) Cf[(size_t)row * N + col] = v;
                } else {
                    __nv_bfloat16 h, l;
                    bf16_split(v, h, l);
                    Ch[(size_t)row * N + col] = h;
                    Cl[(size_t)row * N + col] = l;
                }
            }
        }
        __syncthreads();
    }
#endif
}

// ---------------- weight conversions (to TRANSPOSED planes) ----------------
__global__ void conv_transpose_split(const float* __restrict__ W,
                                     __nv_bfloat16* __restrict__ th,
                                     __nv_bfloat16* __restrict__ tl,
                                     int K, int N, int Npad) {
    __shared__ float t[32][33];
    int l  = blockIdx.z;
    int k0 = blockIdx.y * 32, n0 = blockIdx.x * 32;
    const float* Wl = W + (size_t)l * K * N;
    for (int r = threadIdx.y; r < 32; r += 8) {
        int k = k0 + r, n = n0 + threadIdx.x;
        t[r][threadIdx.x] = (k < K && n < N) ? Wl[(size_t)k * N + n] : 0.0f;
    }
    __syncthreads();
    __nv_bfloat16* thl = th + (size_t)l * Npad * K;
    __nv_bfloat16* tll = tl + (size_t)l * Npad * K;
    for (int r = threadIdx.y; r < 32; r += 8) {
        int n = n0 + r, k = k0 + threadIdx.x;
        if (n < Npad && k < K) {
            __nv_bfloat16 h, lo;
            bf16_split(t[threadIdx.x][r], h, lo);
            thl[(size_t)n * K + k] = h;
            tll[(size_t)n * K + k] = lo;
        }
    }
}

__global__ void pack_qkv_t_kernel(const float* __restrict__ Wq,
                                  const float* __restrict__ Wk,
                                  const float* __restrict__ Wv) {
    int idx = blockIdx.x * blockDim.x + threadIdx.x;
    const int per_l = 3 * D_ * D_;
    if (idx >= L_ * per_l) return;
    int l = idx / per_l;
    int r = idx % per_l;
    int n = r / D_;
    int k = r % D_;
    int which = n / D_;
    int j = n % D_;
    int h = j / DH_;
    int e = j % DH_;
    const float* W = (which == 0) ? Wq : (which == 1) ? Wk : Wv;
    float v = W[(((size_t)l * H_ + h) * D_ + k) * DH_ + e];
    bf16_split(v, g_wqkv_h[idx], g_wqkv_l[idx]);
}

// ---------------- embedding ----------------
__global__ void embed_kernel(const int* __restrict__ index,
                             const float* __restrict__ tok_emb,
                             const float* __restrict__ pos_emb) {
    int i = blockIdx.x * blockDim.x + threadIdx.x;
    if (i >= BT_ * D_) return;
    int row = i / D_;
    int d   = i % D_;
    int t   = row % T_;
    float v = tok_emb[(size_t)index[row] * D_ + d] + pos_emb[t * D_ + d];
    g_x[i] = v;
    bf16_split(v, g_xh[i], g_xl[i]);
}

// ---------------- attention ----------------
__global__ __launch_bounds__(128)
void attn_kernel() {
    int tq = blockIdx.x;
    int bh = blockIdx.y;
    int b = bh / H_;
    int h = bh % H_;
    int tid = threadIdx.x;

    __shared__ float sc[T_];
    __shared__ float red[128];
    __shared__ float qs[DH_];
    __shared__ float oacc[128];

    const int base = (b * T_) * (3 * D_);
    if (tid < DH_) qs[tid] = g_qkv[(size_t)(b * T_ + tq) * (3 * D_) + h * DH_ + tid];
    __syncthreads();

    const float scale = rsqrtf((float)DH_);

    float lmax = -INFINITY;
    for (int ts = tid; ts <= tq; ts += 128) {
        const float* kp = &g_qkv[(size_t)base + (size_t)ts * (3 * D_) + D_ + h * DH_];
        float s = 0.0f;
#pragma unroll
        for (int e = 0; e < DH_; e++) s += qs[e] * kp[e];
        s *= scale;
        sc[ts] = s;
        lmax = fmaxf(lmax, s);
    }
    red[tid] = lmax;
    __syncthreads();
    for (int o = 64; o > 0; o >>= 1) {
        if (tid < o) red[tid] = fmaxf(red[tid], red[tid + o]);
        __syncthreads();
    }
    float m = red[0];
    __syncthreads();

    float lsum = 0.0f;
    for (int ts = tid; ts <= tq; ts += 128) {
        float p = __expf(sc[ts] - m);
        sc[ts] = p;
        lsum += p;
    }
    red[tid] = lsum;
    __syncthreads();
    for (int o = 64; o > 0; o >>= 1) {
        if (tid < o) red[tid] += red[tid + o];
        __syncthreads();
    }
    float inv = 1.0f / red[0];
    __syncthreads();

    float acc = 0.0f;
    if (tid < 120) {
        int e = tid % DH_;
        int r = tid / DH_;
        for (int ts = r; ts <= tq; ts += 5) {
            acc += sc[ts] * g_qkv[(size_t)base + (size_t)ts * (3 * D_) + 2 * D_ + h * DH_ + e];
        }
    }
    oacc[tid] = (tid < 120) ? acc : 0.0f;
    __syncthreads();
    if (tid < DH_) {
        float o = (oacc[tid] + oacc[tid + 24] + oacc[tid + 48] +
                   oacc[tid + 72] + oacc[tid + 96]) * inv;
        size_t idx = (size_t)(b * T_ + tq) * D_ + h * DH_ + tid;
        bf16_split(o, g_oh[idx], g_ol[idx]);
    }
}

// ---------------- fused residual-add + LayerNorm ----------------
__global__ __launch_bounds__(128)
void add_ln_kernel(const float* __restrict__ x, const float* __restrict__ y,
                   const float* __restrict__ g, const float* __restrict__ bta,
                   float* __restrict__ outf, int write_planes) {
    int row = blockIdx.x;
    int tid = threadIdx.x;
    __shared__ float buf[D_];
    __shared__ float red[128];

    float s = 0.0f;
#pragma unroll
    for (int i = 0; i < D_ / 128; i++) {
        int d = tid + i * 128;
        float t = x[(size_t)row * D_ + d];
        if (y) t += y[(size_t)row * D_ + d];
        buf[d] = t;
        s += t;
    }
    red[tid] = s;
    __syncthreads();
    for (int o = 64; o > 0; o >>= 1) {
        if (tid < o) red[tid] += red[tid + o];
        __syncthreads();
    }
    float mean = red[0] / D_;
    __syncthreads();

    float s2 = 0.0f;
#pragma unroll
    for (int i = 0; i < D_ / 128; i++) {
        int d = tid + i * 128;
        float t = buf[d] - mean;
        s2 += t * t;
    }
    red[tid] = s2;
    __syncthreads();
    for (int o = 64; o > 0; o >>= 1) {
        if (tid < o) red[tid] += red[tid + o];
        __syncthreads();
    }
    float rstd = rsqrtf(red[0] / D_ + 1e-5f);
    __syncthreads();

#pragma unroll
    for (int i = 0; i < D_ / 128; i++) {
        int d = tid + i * 128;
        float v = (buf[d] - mean) * rstd * g[d] + bta[d];
        size_t idx = (size_t)row * D_ + d;
        if (outf) outf[idx] = v;
        if (write_planes) bf16_split(v, g_xh[idx], g_xl[idx]);
    }
}

// ---------------- loss ----------------
__global__ __launch_bounds__(256)
void row_loss_kernel(const float* __restrict__ logits, const int* __restrict__ targets) {
    int row = blockIdx.x;
    int tid = threadIdx.x;
    int tgt = targets[row];
    const float* lr = logits + (size_t)row * V_;

    __shared__ float sm[256], ss[256];
    __shared__ float szt;

    float m = -INFINITY, s = 0.0f, zt = 0.0f;
    for (int j = tid; j < V_; j += 256) {
        float z = lr[j];
        if (j == tgt) zt = z;
        float nm = fmaxf(m, z);
        s = s * __expf(m - nm) + __expf(z - nm);
        m = nm;
    }
    if ((tgt & 255) == tid) szt = zt;
    sm[tid] = m; ss[tid] = s;
    __syncthreads();
    for (int o = 128; o > 0; o >>= 1) {
        if (tid < o) {
            float m2 = sm[tid + o], s2 = ss[tid + o];
            float nm = fmaxf(sm[tid], m2);
            ss[tid] = ss[tid] * __expf(sm[tid] - nm) + s2 * __expf(m2 - nm);
            sm[tid] = nm;
        }
        __syncthreads();
    }
    if (tid == 0) g_rowloss[row] = (sm[0] + logf(ss[0])) - szt;
}

__global__ __launch_bounds__(256)
void loss_direct_kernel(const float* __restrict__ Wout, const float* __restrict__ bout,
                        const int* __restrict__ targets) {
    int row = blockIdx.x;
    int tid = threadIdx.x;
    int tgt = targets[row];
    __shared__ float xs[D_];
    __shared__ float sm[256], ss[256];
    __shared__ float szt;
    for (int i = tid; i < D_; i += 256)
        xs[i] = __bfloat162float(g_xh[(size_t)row * D_ + i]) +
                __bfloat162float(g_xl[(size_t)row * D_ + i]);
    __syncthreads();

    float m = -INFINITY, s = 0.0f, zt = 0.0f;
    for (int j = tid; j < V_; j += 256) {
        float z = bout[j];
        for (int k = 0; k < D_; k++) z += xs[k] * Wout[(size_t)k * V_ + j];
        if (j == tgt) zt = z;
        float nm = fmaxf(m, z);
        s = s * __expf(m - nm) + __expf(z - nm);
        m = nm;
    }
    if ((tgt & 255) == tid) szt = zt;
    sm[tid] = m; ss[tid] = s;
    __syncthreads();
    for (int o = 128; o > 0; o >>= 1) {
        if (tid < o) {
            float m2 = sm[tid + o], s2 = ss[tid + o];
            float nm = fmaxf(sm[tid], m2);
            ss[tid] = ss[tid] * __expf(sm[tid] - nm) + s2 * __expf(m2 - nm);
            sm[tid] = nm;
        }
        __syncthreads();
    }
    if (tid == 0) g_rowloss[row] = (sm[0] + logf(ss[0])) - szt;
}

__global__ __launch_bounds__(256)
void reduce_loss_kernel(float* __restrict__ out) {
    __shared__ float red[256];
    int tid = threadIdx.x;
    float s = 0.0f;
    for (int i = tid; i < BT_; i += 256) s += g_rowloss[i];
    red[tid] = s;
    __syncthreads();
    for (int o = 128; o > 0; o >>= 1) {
        if (tid < o) red[tid] += red[tid + o];
        __syncthreads();
    }
    if (tid == 0) out[0] = red[0] / (float)BT_;
}

// ---------------- host orchestration ----------------
#define SMEM_NT1 ((2 * (2 + 2 * 1) * 16384) + 1024)   // 132 KB
#define SMEM_NT2 ((2 * (2 + 2 * 2) * 16384) + 1024)   // 197 KB

extern "C" void kernel_launch(void* const* d_in, const int* in_sizes, int n_in,
                              void* d_out, int out_size) {
    const int*   index   = (const int*)  d_in[0];
    const int*   targets = (const int*)  d_in[1];
    const float* tok_emb = (const float*)d_in[2];
    const float* pos_emb = (const float*)d_in[3];
    const float* Wq      = (const float*)d_in[4];
    const float* Wk      = (const float*)d_in[5];
    const float* Wv      = (const float*)d_in[6];
    const float* Wo      = (const float*)d_in[7];
    const float* bo      = (const float*)d_in[8];
    const float* W1      = (const float*)d_in[9];
    const float* b1      = (const float*)d_in[10];
    const float* W2      = (const float*)d_in[11];
    const float* b2      = (const float*)d_in[12];
    const float* ln1_g   = (const float*)d_in[13];
    const float* ln1_b   = (const float*)d_in[14];
    const float* ln2_g   = (const float*)d_in[15];
    const float* ln2_b   = (const float*)d_in[16];
    const float* lnf_g   = (const float*)d_in[17];
    const float* lnf_b   = (const float*)d_in[18];
    const float* Wout    = (const float*)d_in[19];
    const float* bout    = (const float*)d_in[20];
    float* out = (float*)d_out;

    float *x, *qkv, *y;
    __nv_bfloat16 *xh, *xl, *oh, *ol, *hh, *hl;
    __nv_bfloat16 *wqkv_h, *wqkv_l, *wo_h, *wo_l, *w1_h, *w1_l, *w2_h, *w2_l, *wout_h, *wout_l;
    cudaGetSymbolAddress((void**)&x,   g_x);
    cudaGetSymbolAddress((void**)&qkv, g_qkv);
    cudaGetSymbolAddress((void**)&y,   g_y);
    cudaGetSymbolAddress((void**)&xh,  g_xh);   cudaGetSymbolAddress((void**)&xl, g_xl);
    cudaGetSymbolAddress((void**)&oh,  g_oh);   cudaGetSymbolAddress((void**)&ol, g_ol);
    cudaGetSymbolAddress((void**)&hh,  g_hh);   cudaGetSymbolAddress((void**)&hl, g_hl);
    cudaGetSymbolAddress((void**)&wqkv_h, g_wqkv_h); cudaGetSymbolAddress((void**)&wqkv_l, g_wqkv_l);
    cudaGetSymbolAddress((void**)&wo_h,   g_wo_h);   cudaGetSymbolAddress((void**)&wo_l,   g_wo_l);
    cudaGetSymbolAddress((void**)&w1_h,   g_w1_h);   cudaGetSymbolAddress((void**)&w1_l,   g_w1_l);
    cudaGetSymbolAddress((void**)&w2_h,   g_w2_h);   cudaGetSymbolAddress((void**)&w2_l,   g_w2_l);
    cudaGetSymbolAddress((void**)&wout_h, g_wout_h); cudaGetSymbolAddress((void**)&wout_l, g_wout_l);

    cudaFuncSetAttribute(gemm_tc<1>, cudaFuncAttributeMaxDynamicSharedMemorySize, SMEM_NT1);
    cudaFuncSetAttribute(gemm_tc<2>, cudaFuncAttributeMaxDynamicSharedMemorySize, SMEM_NT2);

    // ---- weight conversions (transposed planes)
    {
        int n = L_ * 3 * D_ * D_;
        pack_qkv_t_kernel<<<(n + 255) / 256, 256>>>(Wq, Wk, Wv);
        dim3 tb(32, 8);
        conv_transpose_split<<<dim3(D_ / 32, D_ / 32, L_), tb>>>(Wo, wo_h, wo_l, D_, D_, D_);
        conv_transpose_split<<<dim3(FF_ / 32, D_ / 32, L_), tb>>>(W1, w1_h, w1_l, D_, FF_, FF_);
        conv_transpose_split<<<dim3(D_ / 32, FF_ / 32, L_), tb>>>(W2, w2_h, w2_l, FF_, D_, D_);
        conv_transpose_split<<<dim3(VP_ / 32, D_ / 32, 1), tb>>>(Wout, wout_h, wout_l, D_, V_, VP_);
    }

    // ---- embedding
    {
        int total = BT_ * D_;
        embed_kernel<<<(total + 255) / 256, 256>>>(index, tok_emb, pos_emb);
    }

    const dim3 blk(256);
    const int GY = MP_ / 128;   // 38
    for (int l = 0; l < L_; l++) {
        // qkv = x @ Wqkv  (N=1152, NT=1)
        gemm_tc<1><<<dim3(1152 / 128, GY), blk, SMEM_NT1>>>(
            xh, xl, wqkv_h + (size_t)l * 3 * D_ * D_, wqkv_l + (size_t)l * 3 * D_ * D_,
            nullptr, qkv, nullptr, nullptr, BT_, 3 * D_, D_, 0);
        attn_kernel<<<dim3(T_, B_ * H_), 128>>>();
        // y = o @ Wo + bo (N=384, NT=1)
        gemm_tc<1><<<dim3(D_ / 128, GY), blk, SMEM_NT1>>>(
            oh, ol, wo_h + (size_t)l * D_ * D_, wo_l + (size_t)l * D_ * D_,
            bo + (size_t)l * D_, y, nullptr, nullptr, BT_, D_, D_, 0);
        add_ln_kernel<<<BT_, 128>>>(x, y, ln1_g + (size_t)l * D_, ln1_b + (size_t)l * D_, x, 1);
        // hid = relu(x @ W1 + b1) -> planes (N=1536, NT=2)
        gemm_tc<2><<<dim3(FF_ / 256, GY), blk, SMEM_NT2>>>(
            xh, xl, w1_h + (size_t)l * FF_ * D_, w1_l + (size_t)l * FF_ * D_,
            b1 + (size_t)l * FF_, nullptr, hh, hl, BT_, FF_, D_, 1);
        // y = hid @ W2 + b2 (N=384, K=1536, NT=1)
        gemm_tc<1><<<dim3(D_ / 128, GY), blk, SMEM_NT1>>>(
            hh, hl, w2_h + (size_t)l * D_ * FF_, w2_l + (size_t)l * D_ * FF_,
            b2 + (size_t)l * D_, y, nullptr, nullptr, BT_, D_, FF_, 0);
        add_ln_kernel<<<BT_, 128>>>(x, y, ln2_g + (size_t)l * D_, ln2_b + (size_t)l * D_, x, 1);
    }

    add_ln_kernel<<<BT_, 128>>>(x, nullptr, lnf_g, lnf_b, nullptr, 1);

    const long long LOGITS = (long long)BT_ * V_;
    if ((long long)out_size >= LOGITS) {
        // logits = xf @ Wout + bout (N=50257, NT=2)
        gemm_tc<2><<<dim3(VP_ / 256, GY), blk, SMEM_NT2>>>(
            xh, xl, wout_h, wout_l, bout, out, nullptr, nullptr, BT_, V_, D_, 0);
        if ((long long)out_size > LOGITS) {
            row_loss_kernel<<<BT_, 256>>>(out, targets);
            reduce_loss_kernel<<<1, 256>>>(out + LOGITS);
        }
    } else {
        loss_direct_kernel<<<BT_, 256>>>(Wout, bout, targets);
        reduce_loss_kernel<<<1, 256>>>(out);
    }
}

// round 7
// speedup vs baseline: 1.0008x; 1.0008x over previous
#include <cuda_runtime.h>
#include <cuda_bf16.h>
#include <math.h>
#include <stdint.h>

// ---------------- problem constants ----------------
#define V_ 50257
#define VP_ 50432            // V padded to multiple of 256
#define D_ 384
#define T_ 300
#define B_ 16
#define H_ 16
#define DH_ 24
#define L_ 8
#define FF_ 1536
#define BT_ (B_ * T_)        // 4800
#define MP_ 4864             // BT padded to multiple of 128

// tcgen05 only exists in the arch-specific (sm_103a) compilation pass.
#if defined(__CUDA_ARCH__) && (__CUDA_ARCH__ == 1030) && \
    (defined(__CUDA_ARCH_FEAT_SM103_ALL) || defined(__CUDA_ARCH_SPECIFIC__) || defined(__CUDA_ARCH_FAMILY_SPECIFIC__))
#define TCGEN_OK 1
#else
#define TCGEN_OK 0
#endif

// ---------------- scratch (device globals; no allocation allowed) ---------
__device__ float g_x[BT_ * D_];
__device__ float g_qkv[BT_ * 3 * D_];
__device__ float g_y[BT_ * D_];
__device__ float g_rowloss[BT_];

// activation bf16 planes (padded rows stay zero)
__device__ __nv_bfloat16 g_xh[MP_ * D_],  g_xl[MP_ * D_];
__device__ __nv_bfloat16 g_oh[MP_ * D_],  g_ol[MP_ * D_];
__device__ __nv_bfloat16 g_hh[MP_ * FF_], g_hl[MP_ * FF_];

// TRANSPOSED weight bf16 planes: [N, K] layout (tcgen05 SS: D = A @ B^T)
__device__ __nv_bfloat16 g_wqkv_h[L_ * 3 * D_ * D_], g_wqkv_l[L_ * 3 * D_ * D_];
__device__ __nv_bfloat16 g_wo_h[L_ * D_ * D_],       g_wo_l[L_ * D_ * D_];
__device__ __nv_bfloat16 g_w1_h[L_ * FF_ * D_],      g_w1_l[L_ * FF_ * D_];
__device__ __nv_bfloat16 g_w2_h[L_ * D_ * FF_],      g_w2_l[L_ * D_ * FF_];
__device__ __nv_bfloat16 g_wout_h[VP_ * D_],         g_wout_l[VP_ * D_];

__device__ __forceinline__ void bf16_split(float x, __nv_bfloat16& h, __nv_bfloat16& l) {
    h = __float2bfloat16_rn(x);
    l = __float2bfloat16_rn(x - __bfloat162float(h));
}

// ---------------- PTX helpers ----------------
__device__ __forceinline__ uint32_t smem_u32(const void* p) {
    return (uint32_t)__cvta_generic_to_shared(p);
}

#if TCGEN_OK
__device__ __forceinline__ uint32_t elect1() {
    uint32_t pred;
    asm volatile("{\n\t.reg .pred p;\n\telect.sync _|p, 0xFFFFFFFF;\n\tselp.b32 %0, 1, 0, p;\n\t}"
                 : "=r"(pred));
    return pred;
}
#define TC_ALLOC(sa, n) \
    asm volatile("tcgen05.alloc.cta_group::1.sync.aligned.shared::cta.b32 [%0], %1;" \
                 :: "r"(sa), "r"((uint32_t)(n)) : "memory")
#define TC_RELINQ() \
    asm volatile("tcgen05.relinquish_alloc_permit.cta_group::1.sync.aligned;")
#define TC_DEALLOC(t, n) \
    asm volatile("tcgen05.dealloc.cta_group::1.sync.aligned.b32 %0, %1;" \
                 :: "r"(t), "r"((uint32_t)(n)))
#define TC_COMMIT(mb) \
    asm volatile("tcgen05.commit.cta_group::1.mbarrier::arrive::one.shared::cluster.b64 [%0];" \
                 :: "r"(mb) : "memory")
#define TC_FENCE_AFTER() asm volatile("tcgen05.fence::after_thread_sync;" ::: "memory")
#define FENCE_ASYNC() asm volatile("fence.proxy.async.shared::cta;" ::: "memory")
#define TC_WAIT_LD() asm volatile("tcgen05.wait::ld.sync.aligned;" ::: "memory")
#define MB_INIT(addr, cnt) \
    asm volatile("mbarrier.init.shared.b64 [%0], %1;" :: "r"(addr), "r"((uint32_t)(cnt)) : "memory")
#define MB_INVAL(addr) \
    asm volatile("mbarrier.inval.shared.b64 [%0];" :: "r"(addr) : "memory")
#define MB_WAIT(addr, phase) do {                                                    \
    uint32_t _done;                                                                  \
    asm volatile("{\n\t.reg .pred p;\n\t"                                            \
        "mbarrier.try_wait.parity.acquire.cta.shared::cta.b64 p, [%1], %2;\n\t"      \
        "selp.b32 %0, 1, 0, p;\n\t}"                                                 \
        : "=r"(_done) : "r"(addr), "r"((uint32_t)(phase)) : "memory");               \
    while (!_done) {                                                                 \
        asm volatile("{\n\t.reg .pred p;\n\t"                                        \
            "mbarrier.try_wait.parity.acquire.cta.shared::cta.b64 p, [%1], %2, 0x989680;\n\t" \
            "selp.b32 %0, 1, 0, p;\n\t}"                                             \
            : "=r"(_done) : "r"(addr), "r"((uint32_t)(phase)) : "memory");           \
    } } while (0)

#define TC_LD32(r, addr) \
    asm volatile("tcgen05.ld.sync.aligned.32x32b.x32.b32 " \
        "{%0, %1, %2, %3, %4, %5, %6, %7, %8, %9, %10, %11, %12, %13, %14, %15, " \
        " %16, %17, %18, %19, %20, %21, %22, %23, %24, %25, %26, %27, %28, %29, %30, %31}, [%32];" \
        : "=r"((r)[0]), "=r"((r)[1]), "=r"((r)[2]), "=r"((r)[3]), \
          "=r"((r)[4]), "=r"((r)[5]), "=r"((r)[6]), "=r"((r)[7]), \
          "=r"((r)[8]), "=r"((r)[9]), "=r"((r)[10]), "=r"((r)[11]), \
          "=r"((r)[12]), "=r"((r)[13]), "=r"((r)[14]), "=r"((r)[15]), \
          "=r"((r)[16]), "=r"((r)[17]), "=r"((r)[18]), "=r"((r)[19]), \
          "=r"((r)[20]), "=r"((r)[21]), "=r"((r)[22]), "=r"((r)[23]), \
          "=r"((r)[24]), "=r"((r)[25]), "=r"((r)[26]), "=r"((r)[27]), \
          "=r"((r)[28]), "=r"((r)[29]), "=r"((r)[30]), "=r"((r)[31]) \
        : "r"(addr))

// SS bf16 mma: D[128,128] += A @ B^T  (A,B smem descriptors, SW128)
__device__ __forceinline__ void mma_ss(uint32_t d, uint64_t a, uint64_t b, uint32_t idesc, bool acc) {
    uint32_t en = acc ? 1u : 0u;
    asm volatile("{\n\t.reg .pred p;\n\tsetp.ne.u32 p, %5, 0;\n\t"
        "tcgen05.mma.cta_group::1.kind::f16 [%0], %1, %2, %3, {%4,%4,%4,%4}, p;\n\t}"
        :: "r"(d), "l"(a), "l"(b), "r"(idesc), "r"(0u), "r"(en) : "memory");
}
#endif // TCGEN_OK

// idesc: dtype=F32, atype=btype=BF16, N=128, M=128 (matches 0x490-style encoding)
#define IDESC_128 ((1u << 4) | (1u << 7) | (1u << 10) | ((128u / 8u) << 17) | ((128u / 16u) << 24))
// SW128 K-major smem descriptor base (LBO=1, SBO=64, version=1, layout=SW128)
#define DESC_BASE ((2ull << 61) | (1ull << 46) | (64ull << 32) | (1ull << 16))

// ==================== GEMM: tcgen05 bf16x3 (specific) / fp32 fallback ====
// C[M,N] = A[M,K] @ W[K,N] (+bias, relu). A as bf16 hi/lo planes [Mpad,K];
// W as TRANSPOSED hi/lo planes [Npad,K]. NT = number of 128-col B tiles.
template <int NT>
__global__ __launch_bounds__(256)
void gemm_tc(const __nv_bfloat16* __restrict__ Ahg, const __nv_bfloat16* __restrict__ Alg,
             const __nv_bfloat16* __restrict__ Bhg, const __nv_bfloat16* __restrict__ Blg,
             const float* __restrict__ bias, float* __restrict__ Cf,
             __nv_bfloat16* __restrict__ Ch, __nv_bfloat16* __restrict__ Cl,
             int M, int N, int K, int relu) {
    extern __shared__ char dyn[];
    const int tid  = threadIdx.x;
#if TCGEN_OK
    constexpr int NBUF  = 2 + 2 * NT;     // Ah, Al, {Bh, Bl} x NT
    constexpr int BUFB  = 16384;          // 128 rows x 64 bf16 (SW128)
    constexpr int STAGE = NBUF * BUFB;
    char* sb = (char*)(((uintptr_t)dyn + 1023) & ~(uintptr_t)1023);
    __shared__ uint32_t s_tm[1];
    __shared__ __align__(8) uint64_t s_mb[2];

    const int warp = tid >> 5;
    const int lane = tid & 31;
    const int bm = blockIdx.y * 128;
    const int bn = blockIdx.x * (NT * 128);

    if (warp == 0) { TC_ALLOC(smem_u32(s_tm), 512); TC_RELINQ(); }
    if (tid == 0) { MB_INIT(smem_u32(&s_mb[0]), 1); MB_INIT(smem_u32(&s_mb[1]), 1); }
    __syncthreads();
    const uint32_t tmem = s_tm[0];
    const uint32_t mb0 = smem_u32(&s_mb[0]);
    const uint32_t mb1 = smem_u32(&s_mb[1]);

    const int nst = K >> 6;   // K stages of 64

    auto load_stage = [&](int st, int k0) {
        char* s = sb + st * STAGE;
        for (int i = tid; i < NBUF * 1024; i += 256) {
            int buf = i >> 10, ch = i & 1023;
            int row = ch >> 3, c16 = ch & 7;
            const __nv_bfloat16* src;
            if (buf == 0)      src = Ahg + (size_t)(bm + row) * K + k0 + c16 * 8;
            else if (buf == 1) src = Alg + (size_t)(bm + row) * K + k0 + c16 * 8;
            else {
                int j = (buf - 2) >> 1;
                const __nv_bfloat16* P = ((buf - 2) & 1) ? Blg : Bhg;
                src = P + (size_t)(bn + j * 128 + row) * K + k0 + c16 * 8;
            }
            uint32_t off = row * 128 + c16 * 16;
            uint32_t sw = off ^ ((off >> 3) & 0x70);
            *(uint4*)(s + buf * BUFB + sw) = *(const uint4*)src;
        }
    };

    load_stage(0, 0);
    if (nst > 1) load_stage(1, 64);

    int ph0 = 0, ph1 = 0;
    for (int st = 0; st < nst; st++) {
        int b = st & 1;
        FENCE_ASYNC();
        __syncthreads();
        if (warp == 0 && elect1()) {
            char* s = sb + b * STAGE;
            uint64_t ah = DESC_BASE | ((smem_u32(s) >> 4) & 0x3FFF);
            uint64_t al = DESC_BASE | ((smem_u32(s + BUFB) >> 4) & 0x3FFF);
#pragma unroll
            for (int j = 0; j < NT; j++) {
                uint64_t bh = DESC_BASE | ((smem_u32(s + (2 + 2 * j) * BUFB) >> 4) & 0x3FFF);
                uint64_t bl = DESC_BASE | ((smem_u32(s + (3 + 2 * j) * BUFB) >> 4) & 0x3FFF);
                uint32_t dst = tmem + j * 128;
#pragma unroll
                for (int k = 0; k < 4; k++) {
                    bool first = (st == 0) && (k == 0);
                    mma_ss(dst, ah + k * 2, bh + k * 2, IDESC_128, !first);
                    mma_ss(dst, ah + k * 2, bl + k * 2, IDESC_128, true);
                    mma_ss(dst, al + k * 2, bh + k * 2, IDESC_128, true);
                }
            }
            TC_COMMIT(b ? mb1 : mb0);
        }
        if (st + 2 < nst) {
            if (b == 0) { MB_WAIT(mb0, ph0); ph0 ^= 1; }
            else        { MB_WAIT(mb1, ph1); ph1 ^= 1; }
            load_stage(b, (st + 2) << 6);
        }
    }
    {
        int b = (nst - 1) & 1;
        if (b == 0) { MB_WAIT(mb0, ph0); }
        else        { MB_WAIT(mb1, ph1); }
    }
    TC_FENCE_AFTER();
    __syncthreads();

    // ---- epilogue: TMEM -> (smem transpose) -> gmem, coalesced
    const int sub = warp & 3;          // TMEM subpartition (rows 32*sub..)
    const int wg  = warp >> 2;         // column half
    const int NCH = NT * 64;           // cols per warpgroup
    float* smf = (float*)sb;           // reuse stage smem: 2 regions of 128x33 fp32
    for (int chk = 0; chk < NCH / 32; chk++) {
        uint32_t regs[32];
        int coll = wg * NCH + chk * 32;            // local col base
        TC_LD32(regs, tmem + coll);
        TC_WAIT_LD();
        int rl = sub * 32 + lane;
        float* dstp = smf + wg * (128 * 33) + rl * 33;
#pragma unroll
        for (int c = 0; c < 32; c++) {
            float v = __uint_as_float(regs[c]);
            int col = bn + coll + c;
            if (bias && col < N) v += bias[col];
            if (relu) v = fmaxf(v, 0.0f);
            dstp[c] = v;
        }
        __syncthreads();
        for (int e = tid; e < 128 * 64; e += 256) {
            int row = e >> 6;
            int cc  = e & 63;
            int gq  = cc >> 5;
            int c   = cc & 31;
            int col = bn + gq * NCH + chk * 32 + c;
            int grow = bm + row;
            float v = smf[gq * (128 * 33) + row * 33 + c];
            if (Cf) {
                if (grow < M && col < N) Cf[(size_t)grow * N + col] = v;
            } else {
                __nv_bfloat16 h, l;
                bf16_split(v, h, l);
                Ch[(size_t)grow * N + col] = h;
                Cl[(size_t)grow * N + col] = l;
            }
        }
        __syncthreads();
    }

    if (tid == 0) { MB_INVAL(mb0); MB_INVAL(mb1); }
    __syncthreads();
    if (warp == 0) TC_DEALLOC(tmem, 512);
#else
    // ---------- portable fp32 fallback (runs only if generic cubin loads) ----
    float* As = (float*)dyn;           // [8][128]
    float* Bs = As + 8 * 128;          // [8][128]
    const int bm = blockIdx.y * 128;
    const int tx = tid % 16;
    const int ty = tid / 16;

    for (int jt = 0; jt < NT; jt++) {
        const int bn = blockIdx.x * (NT * 128) + jt * 128;
        float acc[8][8];
#pragma unroll
        for (int i = 0; i < 8; i++)
#pragma unroll
            for (int j = 0; j < 8; j++) acc[i][j] = 0.0f;

        const int a_row  = tid >> 1;
        const int a_col4 = (tid & 1) * 4;
        const int b_row  = tid >> 5;
        const int b_col  = (tid & 31) * 4;

        for (int k0 = 0; k0 < K; k0 += 8) {
#pragma unroll
            for (int u = 0; u < 4; u++) {
                int kk = k0 + a_col4 + u;
                size_t ia = (size_t)(bm + a_row) * K + kk;
                As[(a_col4 + u) * 128 + a_row] =
                    __bfloat162float(Ahg[ia]) + __bfloat162float(Alg[ia]);
            }
#pragma unroll
            for (int u = 0; u < 4; u++) {
                int col = bn + b_col + u;
                size_t ib = (size_t)col * K + k0 + b_row;
                Bs[b_row * 128 + b_col + u] =
                    __bfloat162float(Bhg[ib]) + __bfloat162float(Blg[ib]);
            }
            __syncthreads();
#pragma unroll
            for (int kk = 0; kk < 8; kk++) {
                float a[8], bb[8];
#pragma unroll
                for (int i = 0; i < 8; i++) a[i] = As[kk * 128 + ty * 8 + i];
#pragma unroll
                for (int j = 0; j < 8; j++) bb[j] = Bs[kk * 128 + tx * 8 + j];
#pragma unroll
                for (int i = 0; i < 8; i++)
#pragma unroll
                    for (int j = 0; j < 8; j++) acc[i][j] += a[i] * bb[j];
            }
            __syncthreads();
        }

#pragma unroll
        for (int i = 0; i < 8; i++) {
            int row = bm + ty * 8 + i;
#pragma unroll
            for (int j = 0; j < 8; j++) {
                int col = bn + tx * 8 + j;
                float v = acc[i][j];
                if (bias && col < N) v += bias[col];
                if (relu) v = fmaxf(v, 0.0f);
                if (Cf) {
                    if (row < M && col < N) Cf[(size_t)row * N + col] = v;
                } else {
                    __nv_bfloat16 h, l;
                    bf16_split(v, h, l);
                    Ch[(size_t)row * N + col] = h;
                    Cl[(size_t)row * N + col] = l;
                }
            }
        }
        __syncthreads();
    }
#endif
}

// ---------------- weight conversions (to TRANSPOSED planes) ----------------
__global__ void conv_transpose_split(const float* __restrict__ W,
                                     __nv_bfloat16* __restrict__ th,
                                     __nv_bfloat16* __restrict__ tl,
                                     int K, int N, int Npad) {
    __shared__ float t[32][33];
    int l  = blockIdx.z;
    int k0 = blockIdx.y * 32, n0 = blockIdx.x * 32;
    const float* Wl = W + (size_t)l * K * N;
    for (int r = threadIdx.y; r < 32; r += 8) {
        int k = k0 + r, n = n0 + threadIdx.x;
        t[r][threadIdx.x] = (k < K && n < N) ? Wl[(size_t)k * N + n] : 0.0f;
    }
    __syncthreads();
    __nv_bfloat16* thl = th + (size_t)l * Npad * K;
    __nv_bfloat16* tll = tl + (size_t)l * Npad * K;
    for (int r = threadIdx.y; r < 32; r += 8) {
        int n = n0 + r, k = k0 + threadIdx.x;
        if (n < Npad && k < K) {
            __nv_bfloat16 h, lo;
            bf16_split(t[threadIdx.x][r], h, lo);
            thl[(size_t)n * K + k] = h;
            tll[(size_t)n * K + k] = lo;
        }
    }
}

__global__ void pack_qkv_t_kernel(const float* __restrict__ Wq,
                                  const float* __restrict__ Wk,
                                  const float* __restrict__ Wv) {
    int idx = blockIdx.x * blockDim.x + threadIdx.x;
    const int per_l = 3 * D_ * D_;
    if (idx >= L_ * per_l) return;
    int l = idx / per_l;
    int r = idx % per_l;
    int n = r / D_;
    int k = r % D_;
    int which = n / D_;
    int j = n % D_;
    int h = j / DH_;
    int e = j % DH_;
    const float* W = (which == 0) ? Wq : (which == 1) ? Wk : Wv;
    float v = W[(((size_t)l * H_ + h) * D_ + k) * DH_ + e];
    bf16_split(v, g_wqkv_h[idx], g_wqkv_l[idx]);
}

// ---------------- embedding ----------------
__global__ void embed_kernel(const int* __restrict__ index,
                             const float* __restrict__ tok_emb,
                             const float* __restrict__ pos_emb) {
    int i = blockIdx.x * blockDim.x + threadIdx.x;
    if (i >= BT_ * D_) return;
    int row = i / D_;
    int d   = i % D_;
    int t   = row % T_;
    float v = tok_emb[(size_t)index[row] * D_ + d] + pos_emb[t * D_ + d];
    g_x[i] = v;
    bf16_split(v, g_xh[i], g_xl[i]);
}

// ---------------- attention ----------------
__global__ __launch_bounds__(128)
void attn_kernel() {
    int tq = blockIdx.x;
    int bh = blockIdx.y;
    int b = bh / H_;
    int h = bh % H_;
    int tid = threadIdx.x;

    __shared__ float sc[T_];
    __shared__ float red[128];
    __shared__ float qs[DH_];
    __shared__ float oacc[128];

    const int base = (b * T_) * (3 * D_);
    if (tid < DH_) qs[tid] = g_qkv[(size_t)(b * T_ + tq) * (3 * D_) + h * DH_ + tid];
    __syncthreads();

    const float scale = rsqrtf((float)DH_);

    float lmax = -INFINITY;
    for (int ts = tid; ts <= tq; ts += 128) {
        const float* kp = &g_qkv[(size_t)base + (size_t)ts * (3 * D_) + D_ + h * DH_];
        float s = 0.0f;
#pragma unroll
        for (int e = 0; e < DH_; e++) s += qs[e] * kp[e];
        s *= scale;
        sc[ts] = s;
        lmax = fmaxf(lmax, s);
    }
    red[tid] = lmax;
    __syncthreads();
    for (int o = 64; o > 0; o >>= 1) {
        if (tid < o) red[tid] = fmaxf(red[tid], red[tid + o]);
        __syncthreads();
    }
    float m = red[0];
    __syncthreads();

    float lsum = 0.0f;
    for (int ts = tid; ts <= tq; ts += 128) {
        float p = __expf(sc[ts] - m);
        sc[ts] = p;
        lsum += p;
    }
    red[tid] = lsum;
    __syncthreads();
    for (int o = 64; o > 0; o >>= 1) {
        if (tid < o) red[tid] += red[tid + o];
        __syncthreads();
    }
    float inv = 1.0f / red[0];
    __syncthreads();

    float acc = 0.0f;
    if (tid < 120) {
        int e = tid % DH_;
        int r = tid / DH_;
        for (int ts = r; ts <= tq; ts += 5) {
            acc += sc[ts] * g_qkv[(size_t)base + (size_t)ts * (3 * D_) + 2 * D_ + h * DH_ + e];
        }
    }
    oacc[tid] = (tid < 120) ? acc : 0.0f;
    __syncthreads();
    if (tid < DH_) {
        float o = (oacc[tid] + oacc[tid + 24] + oacc[tid + 48] +
                   oacc[tid + 72] + oacc[tid + 96]) * inv;
        size_t idx = (size_t)(b * T_ + tq) * D_ + h * DH_ + tid;
        bf16_split(o, g_oh[idx], g_ol[idx]);
    }
}

// ---------------- fused residual-add + LayerNorm ----------------
__global__ __launch_bounds__(128)
void add_ln_kernel(const float* __restrict__ x, const float* __restrict__ y,
                   const float* __restrict__ g, const float* __restrict__ bta,
                   float* __restrict__ outf, int write_planes) {
    int row = blockIdx.x;
    int tid = threadIdx.x;
    __shared__ float buf[D_];
    __shared__ float red[128];

    float s = 0.0f;
#pragma unroll
    for (int i = 0; i < D_ / 128; i++) {
        int d = tid + i * 128;
        float t = x[(size_t)row * D_ + d];
        if (y) t += y[(size_t)row * D_ + d];
        buf[d] = t;
        s += t;
    }
    red[tid] = s;
    __syncthreads();
    for (int o = 64; o > 0; o >>= 1) {
        if (tid < o) red[tid] += red[tid + o];
        __syncthreads();
    }
    float mean = red[0] / D_;
    __syncthreads();

    float s2 = 0.0f;
#pragma unroll
    for (int i = 0; i < D_ / 128; i++) {
        int d = tid + i * 128;
        float t = buf[d] - mean;
        s2 += t * t;
    }
    red[tid] = s2;
    __syncthreads();
    for (int o = 64; o > 0; o >>= 1) {
        if (tid < o) red[tid] += red[tid + o];
        __syncthreads();
    }
    float rstd = rsqrtf(red[0] / D_ + 1e-5f);
    __syncthreads();

#pragma unroll
    for (int i = 0; i < D_ / 128; i++) {
        int d = tid + i * 128;
        float v = (buf[d] - mean) * rstd * g[d] + bta[d];
        size_t idx = (size_t)row * D_ + d;
        if (outf) outf[idx] = v;
        if (write_planes) bf16_split(v, g_xh[idx], g_xl[idx]);
    }
}

// ---------------- loss ----------------
__global__ __launch_bounds__(256)
void row_loss_kernel(const float* __restrict__ logits, const int* __restrict__ targets) {
    int row = blockIdx.x;
    int tid = threadIdx.x;
    int tgt = targets[row];
    const float* lr = logits + (size_t)row * V_;

    __shared__ float sm[256], ss[256];
    __shared__ float szt;

    float m = -INFINITY, s = 0.0f, zt = 0.0f;
    for (int j = tid; j < V_; j += 256) {
        float z = lr[j];
        if (j == tgt) zt = z;
        float nm = fmaxf(m, z);
        s = s * __expf(m - nm) + __expf(z - nm);
        m = nm;
    }
    if ((tgt & 255) == tid) szt = zt;
    sm[tid] = m; ss[tid] = s;
    __syncthreads();
    for (int o = 128; o > 0; o >>= 1) {
        if (tid < o) {
            float m2 = sm[tid + o], s2 = ss[tid + o];
            float nm = fmaxf(sm[tid], m2);
            ss[tid] = ss[tid] * __expf(sm[tid] - nm) + s2 * __expf(m2 - nm);
            sm[tid] = nm;
        }
        __syncthreads();
    }
    if (tid == 0) g_rowloss[row] = (sm[0] + logf(ss[0])) - szt;
}

__global__ __launch_bounds__(256)
void loss_direct_kernel(const float* __restrict__ Wout, const float* __restrict__ bout,
                        const int* __restrict__ targets) {
    int row = blockIdx.x;
    int tid = threadIdx.x;
    int tgt = targets[row];
    __shared__ float xs[D_];
    __shared__ float sm[256], ss[256];
    __shared__ float szt;
    for (int i = tid; i < D_; i += 256)
        xs[i] = __bfloat162float(g_xh[(size_t)row * D_ + i]) +
                __bfloat162float(g_xl[(size_t)row * D_ + i]);
    __syncthreads();

    float m = -INFINITY, s = 0.0f, zt = 0.0f;
    for (int j = tid; j < V_; j += 256) {
        float z = bout[j];
        for (int k = 0; k < D_; k++) z += xs[k] * Wout[(size_t)k * V_ + j];
        if (j == tgt) zt = z;
        float nm = fmaxf(m, z);
        s = s * __expf(m - nm) + __expf(z - nm);
        m = nm;
    }
    if ((tgt & 255) == tid) szt = zt;
    sm[tid] = m; ss[tid] = s;
    __syncthreads();
    for (int o = 128; o > 0; o >>= 1) {
        if (tid < o) {
            float m2 = sm[tid + o], s2 = ss[tid + o];
            float nm = fmaxf(sm[tid], m2);
            ss[tid] = ss[tid] * __expf(sm[tid] - nm) + s2 * __expf(m2 - nm);
            sm[tid] = nm;
        }
        __syncthreads();
    }
    if (tid == 0) g_rowloss[row] = (sm[0] + logf(ss[0])) - szt;
}

__global__ __launch_bounds__(256)
void reduce_loss_kernel(float* __restrict__ out) {
    __shared__ float red[256];
    int tid = threadIdx.x;
    float s = 0.0f;
    for (int i = tid; i < BT_; i += 256) s += g_rowloss[i];
    red[tid] = s;
    __syncthreads();
    for (int o = 128; o > 0; o >>= 1) {
        if (tid < o) red[tid] += red[tid + o];
        __syncthreads();
    }
    if (tid == 0) out[0] = red[0] / (float)BT_;
}

// ---------------- host orchestration ----------------
#define SMEM_NT1 ((2 * (2 + 2 * 1) * 16384) + 1024)   // 132 KB
#define SMEM_NT2 ((2 * (2 + 2 * 2) * 16384) + 1024)   // 197 KB

extern "C" void kernel_launch(void* const* d_in, const int* in_sizes, int n_in,
                              void* d_out, int out_size) {
    const int*   index   = (const int*)  d_in[0];
    const int*   targets = (const int*)  d_in[1];
    const float* tok_emb = (const float*)d_in[2];
    const float* pos_emb = (const float*)d_in[3];
    const float* Wq      = (const float*)d_in[4];
    const float* Wk      = (const float*)d_in[5];
    const float* Wv      = (const float*)d_in[6];
    const float* Wo      = (const float*)d_in[7];
    const float* bo      = (const float*)d_in[8];
    const float* W1      = (const float*)d_in[9];
    const float* b1      = (const float*)d_in[10];
    const float* W2      = (const float*)d_in[11];
    const float* b2      = (const float*)d_in[12];
    const float* ln1_g   = (const float*)d_in[13];
    const float* ln1_b   = (const float*)d_in[14];
    const float* ln2_g   = (const float*)d_in[15];
    const float* ln2_b   = (const float*)d_in[16];
    const float* lnf_g   = (const float*)d_in[17];
    const float* lnf_b   = (const float*)d_in[18];
    const float* Wout    = (const float*)d_in[19];
    const float* bout    = (const float*)d_in[20];
    float* out = (float*)d_out;

    float *x, *qkv, *y;
    __nv_bfloat16 *xh, *xl, *oh, *ol, *hh, *hl;
    __nv_bfloat16 *wqkv_h, *wqkv_l, *wo_h, *wo_l, *w1_h, *w1_l, *w2_h, *w2_l, *wout_h, *wout_l;
    cudaGetSymbolAddress((void**)&x,   g_x);
    cudaGetSymbolAddress((void**)&qkv, g_qkv);
    cudaGetSymbolAddress((void**)&y,   g_y);
    cudaGetSymbolAddress((void**)&xh,  g_xh);   cudaGetSymbolAddress((void**)&xl, g_xl);
    cudaGetSymbolAddress((void**)&oh,  g_oh);   cudaGetSymbolAddress((void**)&ol, g_ol);
    cudaGetSymbolAddress((void**)&hh,  g_hh);   cudaGetSymbolAddress((void**)&hl, g_hl);
    cudaGetSymbolAddress((void**)&wqkv_h, g_wqkv_h); cudaGetSymbolAddress((void**)&wqkv_l, g_wqkv_l);
    cudaGetSymbolAddress((void**)&wo_h,   g_wo_h);   cudaGetSymbolAddress((void**)&wo_l,   g_wo_l);
    cudaGetSymbolAddress((void**)&w1_h,   g_w1_h);   cudaGetSymbolAddress((void**)&w1_l,   g_w1_l);
    cudaGetSymbolAddress((void**)&w2_h,   g_w2_h);   cudaGetSymbolAddress((void**)&w2_l,   g_w2_l);
    cudaGetSymbolAddress((void**)&wout_h, g_wout_h); cudaGetSymbolAddress((void**)&wout_l, g_wout_l);

    cudaFuncSetAttribute(gemm_tc<1>, cudaFuncAttributeMaxDynamicSharedMemorySize, SMEM_NT1);
    cudaFuncSetAttribute(gemm_tc<2>, cudaFuncAttributeMaxDynamicSharedMemorySize, SMEM_NT2);

    // ---- weight conversions (transposed planes)
    {
        int n = L_ * 3 * D_ * D_;
        pack_qkv_t_kernel<<<(n + 255) / 256, 256>>>(Wq, Wk, Wv);
        dim3 tb(32, 8);
        conv_transpose_split<<<dim3(D_ / 32, D_ / 32, L_), tb>>>(Wo, wo_h, wo_l, D_, D_, D_);
        conv_transpose_split<<<dim3(FF_ / 32, D_ / 32, L_), tb>>>(W1, w1_h, w1_l, D_, FF_, FF_);
        conv_transpose_split<<<dim3(D_ / 32, FF_ / 32, L_), tb>>>(W2, w2_h, w2_l, FF_, D_, D_);
        conv_transpose_split<<<dim3(VP_ / 32, D_ / 32, 1), tb>>>(Wout, wout_h, wout_l, D_, V_, VP_);
    }

    // ---- embedding
    {
        int total = BT_ * D_;
        embed_kernel<<<(total + 255) / 256, 256>>>(index, tok_emb, pos_emb);
    }

    const dim3 blk(256);
    const int GY = MP_ / 128;   // 38
    for (int l = 0; l < L_; l++) {
        // qkv = x @ Wqkv  (N=1152, NT=1)
        gemm_tc<1><<<dim3(1152 / 128, GY), blk, SMEM_NT1>>>(
            xh, xl, wqkv_h + (size_t)l * 3 * D_ * D_, wqkv_l + (size_t)l * 3 * D_ * D_,
            nullptr, qkv, nullptr, nullptr, BT_, 3 * D_, D_, 0);
        attn_kernel<<<dim3(T_, B_ * H_), 128>>>();
        // y = o @ Wo + bo (N=384, NT=1)
        gemm_tc<1><<<dim3(D_ / 128, GY), blk, SMEM_NT1>>>(
            oh, ol, wo_h + (size_t)l * D_ * D_, wo_l + (size_t)l * D_ * D_,
            bo + (size_t)l * D_, y, nullptr, nullptr, BT_, D_, D_, 0);
        add_ln_kernel<<<BT_, 128>>>(x, y, ln1_g + (size_t)l * D_, ln1_b + (size_t)l * D_, x, 1);
        // hid = relu(x @ W1 + b1) -> planes (N=1536, NT=2)
        gemm_tc<2><<<dim3(FF_ / 256, GY), blk, SMEM_NT2>>>(
            xh, xl, w1_h + (size_t)l * FF_ * D_, w1_l + (size_t)l * FF_ * D_,
            b1 + (size_t)l * FF_, nullptr, hh, hl, BT_, FF_, D_, 1);
        // y = hid @ W2 + b2 (N=384, K=1536, NT=1)
        gemm_tc<1><<<dim3(D_ / 128, GY), blk, SMEM_NT1>>>(
            hh, hl, w2_h + (size_t)l * D_ * FF_, w2_l + (size_t)l * D_ * FF_,
            b2 + (size_t)l * D_, y, nullptr, nullptr, BT_, D_, FF_, 0);
        add_ln_kernel<<<BT_, 128>>>(x, y, ln2_g + (size_t)l * D_, ln2_b + (size_t)l * D_, x, 1);
    }

    add_ln_kernel<<<BT_, 128>>>(x, nullptr, lnf_g, lnf_b, nullptr, 1);

    const long long LOGITS = (long long)BT_ * V_;
    if ((long long)out_size >= LOGITS) {
        // logits = xf @ Wout + bout (N=50257, NT=2)
        gemm_tc<2><<<dim3(VP_ / 256, GY), blk, SMEM_NT2>>>(
            xh, xl, wout_h, wout_l, bout, out, nullptr, nullptr, BT_, V_, D_, 0);
        if ((long long)out_size > LOGITS) {
            row_loss_kernel<<<BT_, 256>>>(out, targets);
            reduce_loss_kernel<<<1, 256>>>(out + LOGITS);
        }
    } else {
        loss_direct_kernel<<<BT_, 256>>>(Wout, bout, targets);
        reduce_loss_kernel<<<1, 256>>>(out);
    }
}

// round 8
// speedup vs baseline: 1.3528x; 1.3518x over previous
#include <cuda_runtime.h>
#include <cuda_bf16.h>
#include <math.h>
#include <stdint.h>

// ---------------- problem constants ----------------
#define V_ 50257
#define VP_ 50304            // V padded to multiple of 128
#define D_ 384
#define T_ 300
#define B_ 16
#define H_ 16
#define DH_ 24
#define L_ 8
#define FF_ 1536
#define BT_ (B_ * T_)        // 4800
#define MP_ 4864             // BT padded to multiple of 128

// ---------------- scratch (device globals; no allocation allowed) ---------
__device__ float g_x[BT_ * D_];
__device__ float g_qkv[BT_ * 3 * D_];
__device__ float g_y[BT_ * D_];
__device__ float g_rowloss[BT_];

__device__ __nv_bfloat16 g_xh[MP_ * D_],  g_xl[MP_ * D_];
__device__ __nv_bfloat16 g_oh[MP_ * D_],  g_ol[MP_ * D_];
__device__ __nv_bfloat16 g_hh[MP_ * FF_], g_hl[MP_ * FF_];

// weight bf16 planes, [K, Npad] layout
__device__ __nv_bfloat16 g_wqkv_h[L_ * D_ * 3 * D_], g_wqkv_l[L_ * D_ * 3 * D_];
__device__ __nv_bfloat16 g_wo_h[L_ * D_ * D_],       g_wo_l[L_ * D_ * D_];
__device__ __nv_bfloat16 g_w1_h[L_ * D_ * FF_],      g_w1_l[L_ * D_ * FF_];
__device__ __nv_bfloat16 g_w2_h[L_ * FF_ * D_],      g_w2_l[L_ * FF_ * D_];
__device__ __nv_bfloat16 g_wout_h[D_ * VP_],         g_wout_l[D_ * VP_];

__device__ __forceinline__ void bf16_split(float x, __nv_bfloat16& h, __nv_bfloat16& l) {
    h = __float2bfloat16_rn(x);
    l = __float2bfloat16_rn(x - __bfloat162float(h));
}

// ---------------- weight conversions ----------------
__global__ void conv_split_kernel(const float* __restrict__ src,
                                  __nv_bfloat16* __restrict__ dh,
                                  __nv_bfloat16* __restrict__ dl, int n) {
    int i = blockIdx.x * blockDim.x + threadIdx.x;
    if (i >= n) return;
    bf16_split(src[i], dh[i], dl[i]);
}

__global__ void pack_qkv_bf16_kernel(const float* __restrict__ Wq,
                                     const float* __restrict__ Wk,
                                     const float* __restrict__ Wv) {
    int idx = blockIdx.x * blockDim.x + threadIdx.x;
    const int per_l = D_ * 3 * D_;
    if (idx >= L_ * per_l) return;
    int l = idx / per_l;
    int r = idx % per_l;
    int d = r / (3 * D_);
    int c = r % (3 * D_);
    int which = c / D_;
    int j = c % D_;
    int h = j / DH_;
    int e = j % DH_;
    const float* W = (which == 0) ? Wq : (which == 1) ? Wk : Wv;
    float v = W[(((size_t)l * H_ + h) * D_ + d) * DH_ + e];
    bf16_split(v, g_wqkv_h[idx], g_wqkv_l[idx]);
}

__global__ void conv_wout_kernel(const float* __restrict__ Wout) {
    int idx = blockIdx.x * blockDim.x + threadIdx.x;
    if (idx >= D_ * VP_) return;
    int k = idx / VP_;
    int n = idx % VP_;
    float v = (n < V_) ? Wout[(size_t)k * V_ + n] : 0.0f;
    bf16_split(v, g_wout_h[idx], g_wout_l[idx]);
}

// ---------------- embedding ----------------
__global__ void embed_kernel(const int* __restrict__ index,
                             const float* __restrict__ tok_emb,
                             const float* __restrict__ pos_emb) {
    int i = blockIdx.x * blockDim.x + threadIdx.x;
    if (i >= BT_ * D_) return;
    int row = i / D_;
    int d   = i % D_;
    int t   = row % T_;
    float v = tok_emb[(size_t)index[row] * D_ + d] + pos_emb[t * D_ + d];
    g_x[i] = v;
    bf16_split(v, g_xh[i], g_xl[i]);
}

// ==================== bf16x3 GEMM, cp.async multi-stage pipeline ==========
#define BN 128
#define A_PAD 40
#define B_PAD 136

__device__ __forceinline__ uint32_t smem_u32(const void* p) {
    return (uint32_t)__cvta_generic_to_shared(p);
}
__device__ __forceinline__ void cp16(void* sp, const void* gp) {
    asm volatile("cp.async.cg.shared.global [%0], [%1], 16;"
                 :: "r"(smem_u32(sp)), "l"(gp));
}
__device__ __forceinline__ void cp_commit() {
    asm volatile("cp.async.commit_group;");
}
template <int N>
__device__ __forceinline__ void cp_wait() {
    asm volatile("cp.async.wait_group %0;" :: "n"(N));
}
__device__ __forceinline__ void ldm_x4(uint32_t* r, uint32_t addr) {
    asm volatile("ldmatrix.sync.aligned.m8n8.x4.shared.b16 {%0,%1,%2,%3}, [%4];"
                 : "=r"(r[0]), "=r"(r[1]), "=r"(r[2]), "=r"(r[3]) : "r"(addr));
}
__device__ __forceinline__ void ldm_x2_t(uint32_t* r, uint32_t addr) {
    asm volatile("ldmatrix.sync.aligned.m8n8.x2.trans.shared.b16 {%0,%1}, [%2];"
                 : "=r"(r[0]), "=r"(r[1]) : "r"(addr));
}
__device__ __forceinline__ void mma_bf16(float* d, const uint32_t* a, const uint32_t* b) {
    asm volatile("mma.sync.aligned.m16n8k16.row.col.f32.bf16.bf16.f32 "
                 "{%0,%1,%2,%3},{%4,%5,%6,%7},{%8,%9},{%0,%1,%2,%3};"
                 : "+f"(d[0]), "+f"(d[1]), "+f"(d[2]), "+f"(d[3])
                 : "r"(a[0]), "r"(a[1]), "r"(a[2]), "r"(a[3]), "r"(b[0]), "r"(b[1]));
}

// MT: 16-row m-tiles per warp (BM = 32*MT). S: pipeline stages.
template <int MT, int S>
__global__ __launch_bounds__(256, 2)
void gemm_pipe(const __nv_bfloat16* __restrict__ Ahg,
               const __nv_bfloat16* __restrict__ Alg,
               const __nv_bfloat16* __restrict__ Bhg,
               const __nv_bfloat16* __restrict__ Blg,
               const float* __restrict__ bias,
               float* __restrict__ Cf,
               __nv_bfloat16* __restrict__ Ch,
               __nv_bfloat16* __restrict__ Cl,
               int M, int N, int Npad, int K, int relu) {
    constexpr int BM = 32 * MT;
    constexpr int AOFF_H = 0;
    constexpr int AOFF_L = BM * A_PAD;
    constexpr int BOFF_H = 2 * BM * A_PAD;
    constexpr int BOFF_L = 2 * BM * A_PAD + 32 * B_PAD;
    constexpr int STAGE  = 2 * BM * A_PAD + 2 * 32 * B_PAD;
    extern __shared__ __nv_bfloat16 sm[];

    const int tid = threadIdx.x;
    const int warp = tid >> 5;
    const int lane = tid & 31;
    const int wm = (warp >> 2) * (16 * MT);
    const int wn = (warp & 3) * 32;
    const int bm = blockIdx.y * BM;
    const int bn = blockIdx.x * BN;

    float acc[MT][4][4];
#pragma unroll
    for (int i = 0; i < MT; i++)
#pragma unroll
        for (int j = 0; j < 4; j++)
#pragma unroll
            for (int f = 0; f < 4; f++) acc[i][j][f] = 0.0f;

    const int a_r = tid >> 2;
    const int a_c = (tid & 3) * 8;
    const int b_r = tid >> 4;
    const int b_c = (tid & 15) * 8;

    const __nv_bfloat16* pAh = Ahg + (size_t)(bm + a_r) * K + a_c;
    const __nv_bfloat16* pAl = Alg + (size_t)(bm + a_r) * K + a_c;
    const __nv_bfloat16* pBh = Bhg + (size_t)b_r * Npad + bn + b_c;
    const __nv_bfloat16* pBl = Blg + (size_t)b_r * Npad + bn + b_c;
    const size_t aRowK = (size_t)64 * K;
    const size_t bRowN = (size_t)16 * Npad;

    const int niter = K >> 5;

    auto load_stage = [&](int it) {
        const int s = it % S;
        const int k0 = it << 5;
        __nv_bfloat16* st = sm + s * STAGE;
#pragma unroll
        for (int g = 0; g < BM / 64; g++) {
            cp16(&st[AOFF_H + (a_r + g * 64) * A_PAD + a_c], pAh + k0 + g * aRowK);
            cp16(&st[AOFF_L + (a_r + g * 64) * A_PAD + a_c], pAl + k0 + g * aRowK);
        }
        cp16(&st[BOFF_H + b_r * B_PAD + b_c],        pBh + (size_t)k0 * Npad);
        cp16(&st[BOFF_H + (b_r + 16) * B_PAD + b_c], pBh + (size_t)k0 * Npad + bRowN);
        cp16(&st[BOFF_L + b_r * B_PAD + b_c],        pBl + (size_t)k0 * Npad);
        cp16(&st[BOFF_L + (b_r + 16) * B_PAD + b_c], pBl + (size_t)k0 * Npad + bRowN);
    };

    const int f_row = (lane & 7) + ((lane >> 3) & 1) * 8;
    const int f_k8  = (lane >> 4) * 8;
    const int f_brow = lane & 15;

#pragma unroll
    for (int p = 0; p < S - 1; p++) {
        if (p < niter) load_stage(p);
        cp_commit();
    }

    for (int it = 0; it < niter; it++) {
        cp_wait<S - 2>();
        __syncthreads();
        if (it + S - 1 < niter) load_stage(it + S - 1);
        cp_commit();

        const __nv_bfloat16* st = sm + (it % S) * STAGE;
#pragma unroll
        for (int ks = 0; ks < 2; ks++) {
            const int kk = ks * 16;
            uint32_t ah[MT][4], al[MT][4], bh[4][2], bl[4][2];
#pragma unroll
            for (int mt = 0; mt < MT; mt++) {
                int row = wm + mt * 16 + f_row;
                ldm_x4(ah[mt], smem_u32(&st[AOFF_H + row * A_PAD + kk + f_k8]));
                ldm_x4(al[mt], smem_u32(&st[AOFF_L + row * A_PAD + kk + f_k8]));
            }
#pragma unroll
            for (int nt = 0; nt < 4; nt++) {
                int col = wn + nt * 8;
                ldm_x2_t(bh[nt], smem_u32(&st[BOFF_H + (kk + f_brow) * B_PAD + col]));
                ldm_x2_t(bl[nt], smem_u32(&st[BOFF_L + (kk + f_brow) * B_PAD + col]));
            }
#pragma unroll
            for (int mt = 0; mt < MT; mt++)
#pragma unroll
                for (int nt = 0; nt < 4; nt++) {
                    mma_bf16(acc[mt][nt], ah[mt], bh[nt]);
                    mma_bf16(acc[mt][nt], ah[mt], bl[nt]);
                    mma_bf16(acc[mt][nt], al[mt], bh[nt]);
                }
        }
    }

    const int gid = lane >> 2;
    const int tig = lane & 3;
#pragma unroll
    for (int mt = 0; mt < MT; mt++) {
#pragma unroll
        for (int nt = 0; nt < 4; nt++) {
            int row0 = bm + wm + mt * 16 + gid;
            int col0 = bn + wn + nt * 8 + tig * 2;
#pragma unroll
            for (int f = 0; f < 4; f++) {
                int row = row0 + (f >> 1) * 8;
                int col = col0 + (f & 1);
                float v = acc[mt][nt][f];
                if (bias && col < N) v += bias[col];
                if (relu) v = fmaxf(v, 0.0f);
                if (Cf) {
                    if (row < M && col < N) Cf[(size_t)row * N + col] = v;
                } else {
                    __nv_bfloat16 h, l;
                    bf16_split(v, h, l);
                    Ch[(size_t)row * Npad + col] = h;
                    Cl[(size_t)row * Npad + col] = l;
                }
            }
        }
    }
}

// ---------------- attention ----------------
__global__ __launch_bounds__(128)
void attn_kernel() {
    int tq = blockIdx.x;
    int bh = blockIdx.y;
    int b = bh / H_;
    int h = bh % H_;
    int tid = threadIdx.x;

    __shared__ float sc[T_];
    __shared__ float red[128];
    __shared__ float qs[DH_];
    __shared__ float oacc[128];

    const int base = (b * T_) * (3 * D_);
    if (tid < DH_) qs[tid] = g_qkv[(size_t)(b * T_ + tq) * (3 * D_) + h * DH_ + tid];
    __syncthreads();

    const float scale = rsqrtf((float)DH_);

    float lmax = -INFINITY;
    for (int ts = tid; ts <= tq; ts += 128) {
        const float* kp = &g_qkv[(size_t)base + (size_t)ts * (3 * D_) + D_ + h * DH_];
        float s = 0.0f;
#pragma unroll
        for (int e = 0; e < DH_; e++) s += qs[e] * kp[e];
        s *= scale;
        sc[ts] = s;
        lmax = fmaxf(lmax, s);
    }
    red[tid] = lmax;
    __syncthreads();
    for (int o = 64; o > 0; o >>= 1) {
        if (tid < o) red[tid] = fmaxf(red[tid], red[tid + o]);
        __syncthreads();
    }
    float m = red[0];
    __syncthreads();

    float lsum = 0.0f;
    for (int ts = tid; ts <= tq; ts += 128) {
        float p = __expf(sc[ts] - m);
        sc[ts] = p;
        lsum += p;
    }
    red[tid] = lsum;
    __syncthreads();
    for (int o = 64; o > 0; o >>= 1) {
        if (tid < o) red[tid] += red[tid + o];
        __syncthreads();
    }
    float inv = 1.0f / red[0];
    __syncthreads();

    float acc = 0.0f;
    if (tid < 120) {
        int e = tid % DH_;
        int r = tid / DH_;
        for (int ts = r; ts <= tq; ts += 5) {
            acc += sc[ts] * g_qkv[(size_t)base + (size_t)ts * (3 * D_) + 2 * D_ + h * DH_ + e];
        }
    }
    oacc[tid] = (tid < 120) ? acc : 0.0f;
    __syncthreads();
    if (tid < DH_) {
        float o = (oacc[tid] + oacc[tid + 24] + oacc[tid + 48] +
                   oacc[tid + 72] + oacc[tid + 96]) * inv;
        size_t idx = (size_t)(b * T_ + tq) * D_ + h * DH_ + tid;
        bf16_split(o, g_oh[idx], g_ol[idx]);
    }
}

// ---------------- fused residual-add + LayerNorm ----------------
__global__ __launch_bounds__(128)
void add_ln_kernel(const float* __restrict__ x, const float* __restrict__ y,
                   const float* __restrict__ g, const float* __restrict__ bta,
                   float* __restrict__ outf, int write_planes) {
    int row = blockIdx.x;
    int tid = threadIdx.x;
    __shared__ float buf[D_];
    __shared__ float red[128];

    float s = 0.0f;
#pragma unroll
    for (int i = 0; i < D_ / 128; i++) {
        int d = tid + i * 128;
        float t = x[(size_t)row * D_ + d];
        if (y) t += y[(size_t)row * D_ + d];
        buf[d] = t;
        s += t;
    }
    red[tid] = s;
    __syncthreads();
    for (int o = 64; o > 0; o >>= 1) {
        if (tid < o) red[tid] += red[tid + o];
        __syncthreads();
    }
    float mean = red[0] / D_;
    __syncthreads();

    float s2 = 0.0f;
#pragma unroll
    for (int i = 0; i < D_ / 128; i++) {
        int d = tid + i * 128;
        float t = buf[d] - mean;
        s2 += t * t;
    }
    red[tid] = s2;
    __syncthreads();
    for (int o = 64; o > 0; o >>= 1) {
        if (tid < o) red[tid] += red[tid + o];
        __syncthreads();
    }
    float rstd = rsqrtf(red[0] / D_ + 1e-5f);
    __syncthreads();

#pragma unroll
    for (int i = 0; i < D_ / 128; i++) {
        int d = tid + i * 128;
        float v = (buf[d] - mean) * rstd * g[d] + bta[d];
        size_t idx = (size_t)row * D_ + d;
        if (outf) outf[idx] = v;
        if (write_planes) bf16_split(v, g_xh[idx], g_xl[idx]);
    }
}

// ---------------- loss ----------------
__global__ __launch_bounds__(256)
void row_loss_kernel(const float* __restrict__ logits, const int* __restrict__ targets) {
    int row = blockIdx.x;
    int tid = threadIdx.x;
    int tgt = targets[row];
    const float* lr = logits + (size_t)row * V_;

    __shared__ float sm[256], ss[256];
    __shared__ float szt;

    float m = -INFINITY, s = 0.0f, zt = 0.0f;
    for (int j = tid; j < V_; j += 256) {
        float z = lr[j];
        if (j == tgt) zt = z;
        float nm = fmaxf(m, z);
        s = s * __expf(m - nm) + __expf(z - nm);
        m = nm;
    }
    if ((tgt & 255) == tid) szt = zt;
    sm[tid] = m; ss[tid] = s;
    __syncthreads();
    for (int o = 128; o > 0; o >>= 1) {
        if (tid < o) {
            float m2 = sm[tid + o], s2 = ss[tid + o];
            float nm = fmaxf(sm[tid], m2);
            ss[tid] = ss[tid] * __expf(sm[tid] - nm) + s2 * __expf(m2 - nm);
            sm[tid] = nm;
        }
        __syncthreads();
    }
    if (tid == 0) g_rowloss[row] = (sm[0] + logf(ss[0])) - szt;
}

__global__ __launch_bounds__(256)
void loss_direct_kernel(const float* __restrict__ Wout, const float* __restrict__ bout,
                        const int* __restrict__ targets) {
    int row = blockIdx.x;
    int tid = threadIdx.x;
    int tgt = targets[row];
    __shared__ float xs[D_];
    __shared__ float sm[256], ss[256];
    __shared__ float szt;
    for (int i = tid; i < D_; i += 256)
        xs[i] = __bfloat162float(g_xh[(size_t)row * D_ + i]) +
                __bfloat162float(g_xl[(size_t)row * D_ + i]);
    __syncthreads();

    float m = -INFINITY, s = 0.0f, zt = 0.0f;
    for (int j = tid; j < V_; j += 256) {
        float z = bout[j];
        for (int k = 0; k < D_; k++) z += xs[k] * Wout[(size_t)k * V_ + j];
        if (j == tgt) zt = z;
        float nm = fmaxf(m, z);
        s = s * __expf(m - nm) + __expf(z - nm);
        m = nm;
    }
    if ((tgt & 255) == tid) szt = zt;
    sm[tid] = m; ss[tid] = s;
    __syncthreads();
    for (int o = 128; o > 0; o >>= 1) {
        if (tid < o) {
            float m2 = sm[tid + o], s2 = ss[tid + o];
            float nm = fmaxf(sm[tid], m2);
            ss[tid] = ss[tid] * __expf(sm[tid] - nm) + s2 * __expf(m2 - nm);
            sm[tid] = nm;
        }
        __syncthreads();
    }
    if (tid == 0) g_rowloss[row] = (sm[0] + logf(ss[0])) - szt;
}

__global__ __launch_bounds__(256)
void reduce_loss_kernel(float* __restrict__ out) {
    __shared__ float red[256];
    int tid = threadIdx.x;
    float s = 0.0f;
    for (int i = tid; i < BT_; i += 256) s += g_rowloss[i];
    red[tid] = s;
    __syncthreads();
    for (int o = 128; o > 0; o >>= 1) {
        if (tid < o) red[tid] += red[tid + o];
        __syncthreads();
    }
    if (tid == 0) out[0] = red[0] / (float)BT_;
}

// ---------------- host orchestration ----------------
#define SMEM_MT4 (2 * 37888)   // 2 stages x (2*128*40 + 2*32*136)*2B
#define SMEM_MT2 (3 * 27648)   // 3 stages x (2*64*40  + 2*32*136)*2B

extern "C" void kernel_launch(void* const* d_in, const int* in_sizes, int n_in,
                              void* d_out, int out_size) {
    const int*   index   = (const int*)  d_in[0];
    const int*   targets = (const int*)  d_in[1];
    const float* tok_emb = (const float*)d_in[2];
    const float* pos_emb = (const float*)d_in[3];
    const float* Wq      = (const float*)d_in[4];
    const float* Wk      = (const float*)d_in[5];
    const float* Wv      = (const float*)d_in[6];
    const float* Wo      = (const float*)d_in[7];
    const float* bo      = (const float*)d_in[8];
    const float* W1      = (const float*)d_in[9];
    const float* b1      = (const float*)d_in[10];
    const float* W2      = (const float*)d_in[11];
    const float* b2      = (const float*)d_in[12];
    const float* ln1_g   = (const float*)d_in[13];
    const float* ln1_b   = (const float*)d_in[14];
    const float* ln2_g   = (const float*)d_in[15];
    const float* ln2_b   = (const float*)d_in[16];
    const float* lnf_g   = (const float*)d_in[17];
    const float* lnf_b   = (const float*)d_in[18];
    const float* Wout    = (const float*)d_in[19];
    const float* bout    = (const float*)d_in[20];
    float* out = (float*)d_out;

    float *x, *qkv, *y;
    __nv_bfloat16 *xh, *xl, *oh, *ol, *hh, *hl;
    __nv_bfloat16 *wqkv_h, *wqkv_l, *wo_h, *wo_l, *w1_h, *w1_l, *w2_h, *w2_l, *wout_h, *wout_l;
    cudaGetSymbolAddress((void**)&x,   g_x);
    cudaGetSymbolAddress((void**)&qkv, g_qkv);
    cudaGetSymbolAddress((void**)&y,   g_y);
    cudaGetSymbolAddress((void**)&xh,  g_xh);   cudaGetSymbolAddress((void**)&xl, g_xl);
    cudaGetSymbolAddress((void**)&oh,  g_oh);   cudaGetSymbolAddress((void**)&ol, g_ol);
    cudaGetSymbolAddress((void**)&hh,  g_hh);   cudaGetSymbolAddress((void**)&hl, g_hl);
    cudaGetSymbolAddress((void**)&wqkv_h, g_wqkv_h); cudaGetSymbolAddress((void**)&wqkv_l, g_wqkv_l);
    cudaGetSymbolAddress((void**)&wo_h,   g_wo_h);   cudaGetSymbolAddress((void**)&wo_l,   g_wo_l);
    cudaGetSymbolAddress((void**)&w1_h,   g_w1_h);   cudaGetSymbolAddress((void**)&w1_l,   g_w1_l);
    cudaGetSymbolAddress((void**)&w2_h,   g_w2_h);   cudaGetSymbolAddress((void**)&w2_l,   g_w2_l);
    cudaGetSymbolAddress((void**)&wout_h, g_wout_h); cudaGetSymbolAddress((void**)&wout_l, g_wout_l);

    cudaFuncSetAttribute((const void*)gemm_pipe<4, 2>,
                         cudaFuncAttributeMaxDynamicSharedMemorySize, SMEM_MT4);
    cudaFuncSetAttribute((const void*)gemm_pipe<2, 3>,
                         cudaFuncAttributeMaxDynamicSharedMemorySize, SMEM_MT2);

    const dim3 blk(256);
    const int GY4 = MP_ / 128;   // 38
    const int GY2 = MP_ / 64;    // 76

    // ncu capture (-s 5 -c 1, ~2 harness launches ahead) lands on OUR 4th launch:
    // make that the layer-0 qkv GEMM so next round's profile shows the GEMM.
    {
        int total = BT_ * D_;
        embed_kernel<<<(total + 255) / 256, 256>>>(index, tok_emb, pos_emb);     // #1
    }
    {
        int n = L_ * D_ * 3 * D_;
        pack_qkv_bf16_kernel<<<(n + 255) / 256, 256>>>(Wq, Wk, Wv);              // #2
    }
    {
        int n = L_ * D_ * D_;
        conv_split_kernel<<<(n + 255) / 256, 256>>>(Wo, wo_h, wo_l, n);          // #3
    }
    gemm_pipe<4, 2><<<dim3(1152 / BN, GY4), blk, SMEM_MT4>>>(                    // #4 (profiled)
        xh, xl, wqkv_h, wqkv_l, nullptr, qkv, nullptr, nullptr,
        BT_, 3 * D_, 3 * D_, D_, 0);
    {
        int n = L_ * D_ * FF_;
        conv_split_kernel<<<(n + 255) / 256, 256>>>(W1, w1_h, w1_l, n);          // #5
        conv_split_kernel<<<(n + 255) / 256, 256>>>(W2, w2_h, w2_l, n);          // #6
    }

    for (int l = 0; l < L_; l++) {
        if (l > 0) {
            gemm_pipe<4, 2><<<dim3(1152 / BN, GY4), blk, SMEM_MT4>>>(
                xh, xl, wqkv_h + (size_t)l * D_ * 3 * D_, wqkv_l + (size_t)l * D_ * 3 * D_,
                nullptr, qkv, nullptr, nullptr, BT_, 3 * D_, 3 * D_, D_, 0);
        }
        attn_kernel<<<dim3(T_, B_ * H_), 128>>>();
        gemm_pipe<2, 3><<<dim3(D_ / BN, GY2), blk, SMEM_MT2>>>(
            oh, ol, wo_h + (size_t)l * D_ * D_, wo_l + (size_t)l * D_ * D_,
            bo + (size_t)l * D_, y, nullptr, nullptr, BT_, D_, D_, D_, 0);
        add_ln_kernel<<<BT_, 128>>>(x, y, ln1_g + (size_t)l * D_, ln1_b + (size_t)l * D_, x, 1);
        gemm_pipe<4, 2><<<dim3(FF_ / BN, GY4), blk, SMEM_MT4>>>(
            xh, xl, w1_h + (size_t)l * D_ * FF_, w1_l + (size_t)l * D_ * FF_,
            b1 + (size_t)l * FF_, nullptr, hh, hl, BT_, FF_, FF_, D_, 1);
        gemm_pipe<2, 3><<<dim3(D_ / BN, GY2), blk, SMEM_MT2>>>(
            hh, hl, w2_h + (size_t)l * FF_ * D_, w2_l + (size_t)l * FF_ * D_,
            b2 + (size_t)l * D_, y, nullptr, nullptr, BT_, D_, D_, FF_, 0);
        add_ln_kernel<<<BT_, 128>>>(x, y, ln2_g + (size_t)l * D_, ln2_b + (size_t)l * D_, x, 1);
    }

    add_ln_kernel<<<BT_, 128>>>(x, nullptr, lnf_g, lnf_b, nullptr, 1);

    {
        int n = D_ * VP_;
        conv_wout_kernel<<<(n + 255) / 256, 256>>>(Wout);
    }

    const long long LOGITS = (long long)BT_ * V_;
    if ((long long)out_size >= LOGITS) {
        gemm_pipe<4, 2><<<dim3(VP_ / BN, GY4), blk, SMEM_MT4>>>(
            xh, xl, wout_h, wout_l, bout, out, nullptr, nullptr, BT_, V_, VP_, D_, 0);
        if ((long long)out_size > LOGITS) {
            row_loss_kernel<<<BT_, 256>>>(out, targets);
            reduce_loss_kernel<<<1, 256>>>(out + LOGITS);
        }
    } else {
        loss_direct_kernel<<<BT_, 256>>>(Wout, bout, targets);
        reduce_loss_kernel<<<1, 256>>>(out);
    }
}

// round 9
// speedup vs baseline: 3.3945x; 2.5092x over previous
#include <cuda_runtime.h>
#include <cuda_bf16.h>
#include <math.h>
#include <stdint.h>

// ---------------- problem constants ----------------
#define V_ 50257
#define VP_ 50304            // V padded to multiple of 128
#define D_ 384
#define T_ 300
#define B_ 16
#define H_ 16
#define DH_ 24
#define L_ 8
#define FF_ 1536
#define BT_ (B_ * T_)        // 4800
#define MP_ 4864             // BT padded to multiple of 128

// ---------------- scratch (device globals; no allocation allowed) ---------
__device__ float g_x[BT_ * D_];
__device__ float g_qkv[BT_ * 3 * D_];
__device__ float g_y[BT_ * D_];
__device__ float g_rowloss[BT_];

__device__ __nv_bfloat16 g_xh[MP_ * D_],  g_xl[MP_ * D_];
__device__ __nv_bfloat16 g_oh[MP_ * D_],  g_ol[MP_ * D_];
__device__ __nv_bfloat16 g_hh[MP_ * FF_], g_hl[MP_ * FF_];

// weight bf16 planes, [K, Npad] layout
__device__ __nv_bfloat16 g_wqkv_h[L_ * D_ * 3 * D_], g_wqkv_l[L_ * D_ * 3 * D_];
__device__ __nv_bfloat16 g_wo_h[L_ * D_ * D_],       g_wo_l[L_ * D_ * D_];
__device__ __nv_bfloat16 g_w1_h[L_ * D_ * FF_],      g_w1_l[L_ * D_ * FF_];
__device__ __nv_bfloat16 g_w2_h[L_ * FF_ * D_],      g_w2_l[L_ * FF_ * D_];
__device__ __nv_bfloat16 g_wout_h[D_ * VP_],         g_wout_l[D_ * VP_];

__device__ __forceinline__ void bf16_split(float x, __nv_bfloat16& h, __nv_bfloat16& l) {
    h = __float2bfloat16_rn(x);
    l = __float2bfloat16_rn(x - __bfloat162float(h));
}

// ---------------- weight conversions ----------------
__global__ void conv_split_kernel(const float* __restrict__ src,
                                  __nv_bfloat16* __restrict__ dh,
                                  __nv_bfloat16* __restrict__ dl, int n) {
    int i = blockIdx.x * blockDim.x + threadIdx.x;
    if (i >= n) return;
    bf16_split(src[i], dh[i], dl[i]);
}

__global__ void pack_qkv_bf16_kernel(const float* __restrict__ Wq,
                                     const float* __restrict__ Wk,
                                     const float* __restrict__ Wv) {
    int idx = blockIdx.x * blockDim.x + threadIdx.x;
    const int per_l = D_ * 3 * D_;
    if (idx >= L_ * per_l) return;
    int l = idx / per_l;
    int r = idx % per_l;
    int d = r / (3 * D_);
    int c = r % (3 * D_);
    int which = c / D_;
    int j = c % D_;
    int h = j / DH_;
    int e = j % DH_;
    const float* W = (which == 0) ? Wq : (which == 1) ? Wk : Wv;
    float v = W[(((size_t)l * H_ + h) * D_ + d) * DH_ + e];
    bf16_split(v, g_wqkv_h[idx], g_wqkv_l[idx]);
}

__global__ void conv_wout_kernel(const float* __restrict__ Wout) {
    int idx = blockIdx.x * blockDim.x + threadIdx.x;
    if (idx >= D_ * VP_) return;
    int k = idx / VP_;
    int n = idx % VP_;
    float v = (n < V_) ? Wout[(size_t)k * V_ + n] : 0.0f;
    bf16_split(v, g_wout_h[idx], g_wout_l[idx]);
}

// ---------------- embedding ----------------
__global__ void embed_kernel(const int* __restrict__ index,
                             const float* __restrict__ tok_emb,
                             const float* __restrict__ pos_emb) {
    int i = blockIdx.x * blockDim.x + threadIdx.x;
    if (i >= BT_ * D_) return;
    int row = i / D_;
    int d   = i % D_;
    int t   = row % T_;
    float v = tok_emb[(size_t)index[row] * D_ + d] + pos_emb[t * D_ + d];
    g_x[i] = v;
    bf16_split(v, g_xh[i], g_xl[i]);
}

// ==================== bf16x3 GEMM, cp.async multi-stage pipeline ==========
#define BN 128
#define A_PAD 40
#define B_PAD 136

__device__ __forceinline__ uint32_t smem_u32(const void* p) {
    return (uint32_t)__cvta_generic_to_shared(p);
}
__device__ __forceinline__ void cp16(void* sp, const void* gp) {
    asm volatile("cp.async.cg.shared.global [%0], [%1], 16;"
                 :: "r"(smem_u32(sp)), "l"(gp));
}
__device__ __forceinline__ void cp_commit() {
    asm volatile("cp.async.commit_group;");
}
template <int N>
__device__ __forceinline__ void cp_wait() {
    asm volatile("cp.async.wait_group %0;" :: "n"(N));
}
__device__ __forceinline__ void ldm_x4(uint32_t* r, uint32_t addr) {
    asm volatile("ldmatrix.sync.aligned.m8n8.x4.shared.b16 {%0,%1,%2,%3}, [%4];"
                 : "=r"(r[0]), "=r"(r[1]), "=r"(r[2]), "=r"(r[3]) : "r"(addr));
}
__device__ __forceinline__ void ldm_x2_t(uint32_t* r, uint32_t addr) {
    asm volatile("ldmatrix.sync.aligned.m8n8.x2.trans.shared.b16 {%0,%1}, [%2];"
                 : "=r"(r[0]), "=r"(r[1]) : "r"(addr));
}
__device__ __forceinline__ void mma_bf16(float* d, const uint32_t* a, const uint32_t* b) {
    asm volatile("mma.sync.aligned.m16n8k16.row.col.f32.bf16.bf16.f32 "
                 "{%0,%1,%2,%3},{%4,%5,%6,%7},{%8,%9},{%0,%1,%2,%3};"
                 : "+f"(d[0]), "+f"(d[1]), "+f"(d[2]), "+f"(d[3])
                 : "r"(a[0]), "r"(a[1]), "r"(a[2]), "r"(a[3]), "r"(b[0]), "r"(b[1]));
}

// MT: 16-row m-tiles per warp (BM = 32*MT). S: pipeline stages.
template <int MT, int S>
__global__ __launch_bounds__(256, 2)
void gemm_pipe(const __nv_bfloat16* __restrict__ Ahg,
               const __nv_bfloat16* __restrict__ Alg,
               const __nv_bfloat16* __restrict__ Bhg,
               const __nv_bfloat16* __restrict__ Blg,
               const float* __restrict__ bias,
               float* __restrict__ Cf,
               __nv_bfloat16* __restrict__ Ch,
               __nv_bfloat16* __restrict__ Cl,
               int M, int N, int Npad, int K, int relu) {
    constexpr int BM = 32 * MT;
    constexpr int AOFF_H = 0;
    constexpr int AOFF_L = BM * A_PAD;
    constexpr int BOFF_H = 2 * BM * A_PAD;
    constexpr int BOFF_L = 2 * BM * A_PAD + 32 * B_PAD;
    constexpr int STAGE  = 2 * BM * A_PAD + 2 * 32 * B_PAD;
    extern __shared__ __nv_bfloat16 sm[];

    const int tid = threadIdx.x;
    const int warp = tid >> 5;
    const int lane = tid & 31;
    const int wm = (warp >> 2) * (16 * MT);
    const int wn = (warp & 3) * 32;
    const int bm = blockIdx.y * BM;
    const int bn = blockIdx.x * BN;

    float acc[MT][4][4];
#pragma unroll
    for (int i = 0; i < MT; i++)
#pragma unroll
        for (int j = 0; j < 4; j++)
#pragma unroll
            for (int f = 0; f < 4; f++) acc[i][j][f] = 0.0f;

    const int a_r = tid >> 2;
    const int a_c = (tid & 3) * 8;
    const int b_r = tid >> 4;
    const int b_c = (tid & 15) * 8;

    const __nv_bfloat16* pAh = Ahg + (size_t)(bm + a_r) * K + a_c;
    const __nv_bfloat16* pAl = Alg + (size_t)(bm + a_r) * K + a_c;
    const __nv_bfloat16* pBh = Bhg + (size_t)b_r * Npad + bn + b_c;
    const __nv_bfloat16* pBl = Blg + (size_t)b_r * Npad + bn + b_c;
    const size_t aRowK = (size_t)64 * K;
    const size_t bRowN = (size_t)16 * Npad;

    const int niter = K >> 5;

    auto load_stage = [&](int it) {
        const int s = it % S;
        const int k0 = it << 5;
        __nv_bfloat16* st = sm + s * STAGE;
#pragma unroll
        for (int g = 0; g < BM / 64; g++) {
            cp16(&st[AOFF_H + (a_r + g * 64) * A_PAD + a_c], pAh + k0 + g * aRowK);
            cp16(&st[AOFF_L + (a_r + g * 64) * A_PAD + a_c], pAl + k0 + g * aRowK);
        }
        cp16(&st[BOFF_H + b_r * B_PAD + b_c],        pBh + (size_t)k0 * Npad);
        cp16(&st[BOFF_H + (b_r + 16) * B_PAD + b_c], pBh + (size_t)k0 * Npad + bRowN);
        cp16(&st[BOFF_L + b_r * B_PAD + b_c],        pBl + (size_t)k0 * Npad);
        cp16(&st[BOFF_L + (b_r + 16) * B_PAD + b_c], pBl + (size_t)k0 * Npad + bRowN);
    };

    const int f_row = (lane & 7) + ((lane >> 3) & 1) * 8;
    const int f_k8  = (lane >> 4) * 8;
    const int f_brow = lane & 15;

#pragma unroll
    for (int p = 0; p < S - 1; p++) {
        if (p < niter) load_stage(p);
        cp_commit();
    }

    for (int it = 0; it < niter; it++) {
        cp_wait<S - 2>();
        __syncthreads();
        if (it + S - 1 < niter) load_stage(it + S - 1);
        cp_commit();

        const __nv_bfloat16* st = sm + (it % S) * STAGE;
#pragma unroll
        for (int ks = 0; ks < 2; ks++) {
            const int kk = ks * 16;
            uint32_t ah[MT][4], al[MT][4], bh[4][2], bl[4][2];
#pragma unroll
            for (int mt = 0; mt < MT; mt++) {
                int row = wm + mt * 16 + f_row;
                ldm_x4(ah[mt], smem_u32(&st[AOFF_H + row * A_PAD + kk + f_k8]));
                ldm_x4(al[mt], smem_u32(&st[AOFF_L + row * A_PAD + kk + f_k8]));
            }
#pragma unroll
            for (int nt = 0; nt < 4; nt++) {
                int col = wn + nt * 8;
                ldm_x2_t(bh[nt], smem_u32(&st[BOFF_H + (kk + f_brow) * B_PAD + col]));
                ldm_x2_t(bl[nt], smem_u32(&st[BOFF_L + (kk + f_brow) * B_PAD + col]));
            }
#pragma unroll
            for (int mt = 0; mt < MT; mt++)
#pragma unroll
                for (int nt = 0; nt < 4; nt++) {
                    mma_bf16(acc[mt][nt], ah[mt], bh[nt]);
                    mma_bf16(acc[mt][nt], ah[mt], bl[nt]);
                    mma_bf16(acc[mt][nt], al[mt], bh[nt]);
                }
        }
    }

    const int gid = lane >> 2;
    const int tig = lane & 3;
#pragma unroll
    for (int mt = 0; mt < MT; mt++) {
#pragma unroll
        for (int nt = 0; nt < 4; nt++) {
            int row0 = bm + wm + mt * 16 + gid;
            int col0 = bn + wn + nt * 8 + tig * 2;
#pragma unroll
            for (int f = 0; f < 4; f++) {
                int row = row0 + (f >> 1) * 8;
                int col = col0 + (f & 1);
                float v = acc[mt][nt][f];
                if (bias && col < N) v += bias[col];
                if (relu) v = fmaxf(v, 0.0f);
                if (Cf) {
                    if (row < M && col < N) Cf[(size_t)row * N + col] = v;
                } else {
                    __nv_bfloat16 h, l;
                    bf16_split(v, h, l);
                    Ch[(size_t)row * Npad + col] = h;
                    Cl[(size_t)row * Npad + col] = l;
                }
            }
        }
    }
}

// ---------------- attention v2: one block per (b,h), K/V in smem ----------
// smem layout (floats): Kt[24][305] | Vt[24][305] | ps[8][304] | qb[8][24]
#define KT_STRIDE 305
#define ATTN_SMEM_FLOATS (2 * DH_ * KT_STRIDE + 8 * 304 + 8 * DH_)
#define ATTN_SMEM_BYTES  (ATTN_SMEM_FLOATS * 4)

__global__ __launch_bounds__(256)
void attn2_kernel() {
    extern __shared__ float sa[];
    float* Kt = sa;                               // [24][305]
    float* Vt = sa + DH_ * KT_STRIDE;             // [24][305]
    float* ps = sa + 2 * DH_ * KT_STRIDE;         // [8][304]
    float* qb = ps + 8 * 304;                     // [8][24]

    const int bh = blockIdx.x;
    const int b = bh / H_;
    const int h = bh % H_;
    const int tid = threadIdx.x;
    const int warp = tid >> 5;
    const int lane = tid & 31;
    const size_t rowbase = (size_t)(b * T_) * (3 * D_);

    // load K,V transposed (once per block)
    for (int i = tid; i < T_ * DH_; i += 256) {
        int ts = i / DH_, e = i % DH_;
        size_t src = rowbase + (size_t)ts * (3 * D_) + h * DH_ + e;
        Kt[e * KT_STRIDE + ts] = g_qkv[src + D_];
        Vt[e * KT_STRIDE + ts] = g_qkv[src + 2 * D_];
    }
    __syncthreads();

    const float scale = rsqrtf((float)DH_);
    float* psw = ps + warp * 304;
    float* qbw = qb + warp * DH_;

    for (int q = warp; q < T_; q += 8) {
        if (lane < DH_)
            qbw[lane] = g_qkv[rowbase + (size_t)q * (3 * D_) + h * DH_ + lane];
        __syncwarp();

        // scores: lane owns ts = lane + 32j
        float p[10];
        float m = -INFINITY;
#pragma unroll
        for (int j = 0; j < 10; j++) {
            int ts = lane + 32 * j;
            float s = -INFINITY;
            if (ts <= q) {
                float acc = 0.0f;
#pragma unroll
                for (int e = 0; e < DH_; e++)
                    acc += qbw[e] * Kt[e * KT_STRIDE + ts];
                s = acc * scale;
            }
            p[j] = s;
            m = fmaxf(m, s);
        }
#pragma unroll
        for (int o = 16; o > 0; o >>= 1)
            m = fmaxf(m, __shfl_xor_sync(0xffffffff, m, o));

        float lsum = 0.0f;
#pragma unroll
        for (int j = 0; j < 10; j++) {
            int ts = lane + 32 * j;
            float pe = (ts <= q) ? __expf(p[j] - m) : 0.0f;
            if (ts < T_) psw[ts] = pe;
            lsum += pe;
        }
#pragma unroll
        for (int o = 16; o > 0; o >>= 1)
            lsum += __shfl_xor_sync(0xffffffff, lsum, o);
        float inv = 1.0f / lsum;
        __syncwarp();

        // PV: lane = dim
        if (lane < DH_) {
            float acc = 0.0f;
            const float* vrow = Vt + lane * KT_STRIDE;
#pragma unroll 4
            for (int ts = 0; ts <= q; ts++)
                acc += psw[ts] * vrow[ts];
            float o = acc * inv;
            size_t idx = (size_t)(b * T_ + q) * D_ + h * DH_ + lane;
            bf16_split(o, g_oh[idx], g_ol[idx]);
        }
        __syncwarp();   // protect psw/qbw before next query reuses them
    }
}

// ---------------- fused residual-add + LayerNorm ----------------
__global__ __launch_bounds__(128)
void add_ln_kernel(const float* __restrict__ x, const float* __restrict__ y,
                   const float* __restrict__ g, const float* __restrict__ bta,
                   float* __restrict__ outf, int write_planes) {
    int row = blockIdx.x;
    int tid = threadIdx.x;
    __shared__ float buf[D_];
    __shared__ float red[128];

    float s = 0.0f;
#pragma unroll
    for (int i = 0; i < D_ / 128; i++) {
        int d = tid + i * 128;
        float t = x[(size_t)row * D_ + d];
        if (y) t += y[(size_t)row * D_ + d];
        buf[d] = t;
        s += t;
    }
    red[tid] = s;
    __syncthreads();
    for (int o = 64; o > 0; o >>= 1) {
        if (tid < o) red[tid] += red[tid + o];
        __syncthreads();
    }
    float mean = red[0] / D_;
    __syncthreads();

    float s2 = 0.0f;
#pragma unroll
    for (int i = 0; i < D_ / 128; i++) {
        int d = tid + i * 128;
        float t = buf[d] - mean;
        s2 += t * t;
    }
    red[tid] = s2;
    __syncthreads();
    for (int o = 64; o > 0; o >>= 1) {
        if (tid < o) red[tid] += red[tid + o];
        __syncthreads();
    }
    float rstd = rsqrtf(red[0] / D_ + 1e-5f);
    __syncthreads();

#pragma unroll
    for (int i = 0; i < D_ / 128; i++) {
        int d = tid + i * 128;
        float v = (buf[d] - mean) * rstd * g[d] + bta[d];
        size_t idx = (size_t)row * D_ + d;
        if (outf) outf[idx] = v;
        if (write_planes) bf16_split(v, g_xh[idx], g_xl[idx]);
    }
}

// ---------------- loss ----------------
__global__ __launch_bounds__(256)
void row_loss_kernel(const float* __restrict__ logits, const int* __restrict__ targets) {
    int row = blockIdx.x;
    int tid = threadIdx.x;
    int tgt = targets[row];
    const float* lr = logits + (size_t)row * V_;

    __shared__ float sm[256], ss[256];
    __shared__ float szt;

    float m = -INFINITY, s = 0.0f, zt = 0.0f;
    for (int j = tid; j < V_; j += 256) {
        float z = lr[j];
        if (j == tgt) zt = z;
        float nm = fmaxf(m, z);
        s = s * __expf(m - nm) + __expf(z - nm);
        m = nm;
    }
    if ((tgt & 255) == tid) szt = zt;
    sm[tid] = m; ss[tid] = s;
    __syncthreads();
    for (int o = 128; o > 0; o >>= 1) {
        if (tid < o) {
            float m2 = sm[tid + o], s2 = ss[tid + o];
            float nm = fmaxf(sm[tid], m2);
            ss[tid] = ss[tid] * __expf(sm[tid] - nm) + s2 * __expf(m2 - nm);
            sm[tid] = nm;
        }
        __syncthreads();
    }
    if (tid == 0) g_rowloss[row] = (sm[0] + logf(ss[0])) - szt;
}

__global__ __launch_bounds__(256)
void loss_direct_kernel(const float* __restrict__ Wout, const float* __restrict__ bout,
                        const int* __restrict__ targets) {
    int row = blockIdx.x;
    int tid = threadIdx.x;
    int tgt = targets[row];
    __shared__ float xs[D_];
    __shared__ float sm[256], ss[256];
    __shared__ float szt;
    for (int i = tid; i < D_; i += 256)
        xs[i] = __bfloat162float(g_xh[(size_t)row * D_ + i]) +
                __bfloat162float(g_xl[(size_t)row * D_ + i]);
    __syncthreads();

    float m = -INFINITY, s = 0.0f, zt = 0.0f;
    for (int j = tid; j < V_; j += 256) {
        float z = bout[j];
        for (int k = 0; k < D_; k++) z += xs[k] * Wout[(size_t)k * V_ + j];
        if (j == tgt) zt = z;
        float nm = fmaxf(m, z);
        s = s * __expf(m - nm) + __expf(z - nm);
        m = nm;
    }
    if ((tgt & 255) == tid) szt = zt;
    sm[tid] = m; ss[tid] = s;
    __syncthreads();
    for (int o = 128; o > 0; o >>= 1) {
        if (tid < o) {
            float m2 = sm[tid + o], s2 = ss[tid + o];
            float nm = fmaxf(sm[tid], m2);
            ss[tid] = ss[tid] * __expf(sm[tid] - nm) + s2 * __expf(m2 - nm);
            sm[tid] = nm;
        }
        __syncthreads();
    }
    if (tid == 0) g_rowloss[row] = (sm[0] + logf(ss[0])) - szt;
}

__global__ __launch_bounds__(256)
void reduce_loss_kernel(float* __restrict__ out) {
    __shared__ float red[256];
    int tid = threadIdx.x;
    float s = 0.0f;
    for (int i = tid; i < BT_; i += 256) s += g_rowloss[i];
    red[tid] = s;
    __syncthreads();
    for (int o = 128; o > 0; o >>= 1) {
        if (tid < o) red[tid] += red[tid + o];
        __syncthreads();
    }
    if (tid == 0) out[0] = red[0] / (float)BT_;
}

// ---------------- host orchestration ----------------
#define SMEM_MT4 (2 * 37888)   // 2 stages x (2*128*40 + 2*32*136)*2B
#define SMEM_MT2 (3 * 27648)   // 3 stages x (2*64*40  + 2*32*136)*2B

extern "C" void kernel_launch(void* const* d_in, const int* in_sizes, int n_in,
                              void* d_out, int out_size) {
    const int*   index   = (const int*)  d_in[0];
    const int*   targets = (const int*)  d_in[1];
    const float* tok_emb = (const float*)d_in[2];
    const float* pos_emb = (const float*)d_in[3];
    const float* Wq      = (const float*)d_in[4];
    const float* Wk      = (const float*)d_in[5];
    const float* Wv      = (const float*)d_in[6];
    const float* Wo      = (const float*)d_in[7];
    const float* bo      = (const float*)d_in[8];
    const float* W1      = (const float*)d_in[9];
    const float* b1      = (const float*)d_in[10];
    const float* W2      = (const float*)d_in[11];
    const float* b2      = (const float*)d_in[12];
    const float* ln1_g   = (const float*)d_in[13];
    const float* ln1_b   = (const float*)d_in[14];
    const float* ln2_g   = (const float*)d_in[15];
    const float* ln2_b   = (const float*)d_in[16];
    const float* lnf_g   = (const float*)d_in[17];
    const float* lnf_b   = (const float*)d_in[18];
    const float* Wout    = (const float*)d_in[19];
    const float* bout    = (const float*)d_in[20];
    float* out = (float*)d_out;

    float *x, *qkv, *y;
    __nv_bfloat16 *xh, *xl, *oh, *ol, *hh, *hl;
    __nv_bfloat16 *wqkv_h, *wqkv_l, *wo_h, *wo_l, *w1_h, *w1_l, *w2_h, *w2_l, *wout_h, *wout_l;
    cudaGetSymbolAddress((void**)&x,   g_x);
    cudaGetSymbolAddress((void**)&qkv, g_qkv);
    cudaGetSymbolAddress((void**)&y,   g_y);
    cudaGetSymbolAddress((void**)&xh,  g_xh);   cudaGetSymbolAddress((void**)&xl, g_xl);
    cudaGetSymbolAddress((void**)&oh,  g_oh);   cudaGetSymbolAddress((void**)&ol, g_ol);
    cudaGetSymbolAddress((void**)&hh,  g_hh);   cudaGetSymbolAddress((void**)&hl, g_hl);
    cudaGetSymbolAddress((void**)&wqkv_h, g_wqkv_h); cudaGetSymbolAddress((void**)&wqkv_l, g_wqkv_l);
    cudaGetSymbolAddress((void**)&wo_h,   g_wo_h);   cudaGetSymbolAddress((void**)&wo_l,   g_wo_l);
    cudaGetSymbolAddress((void**)&w1_h,   g_w1_h);   cudaGetSymbolAddress((void**)&w1_l,   g_w1_l);
    cudaGetSymbolAddress((void**)&w2_h,   g_w2_h);   cudaGetSymbolAddress((void**)&w2_l,   g_w2_l);
    cudaGetSymbolAddress((void**)&wout_h, g_wout_h); cudaGetSymbolAddress((void**)&wout_l, g_wout_l);

    cudaFuncSetAttribute((const void*)gemm_pipe<4, 2>,
                         cudaFuncAttributeMaxDynamicSharedMemorySize, SMEM_MT4);
    cudaFuncSetAttribute((const void*)gemm_pipe<2, 3>,
                         cudaFuncAttributeMaxDynamicSharedMemorySize, SMEM_MT2);
    cudaFuncSetAttribute((const void*)attn2_kernel,
                         cudaFuncAttributeMaxDynamicSharedMemorySize, ATTN_SMEM_BYTES);

    const dim3 blk(256);
    const int GY4 = MP_ / 128;   // 38
    const int GY2 = MP_ / 64;    // 76

    // keep layer-0 qkv GEMM as launch #4 (the ncu-profiled one)
    {
        int total = BT_ * D_;
        embed_kernel<<<(total + 255) / 256, 256>>>(index, tok_emb, pos_emb);     // #1
    }
    {
        int n = L_ * D_ * 3 * D_;
        pack_qkv_bf16_kernel<<<(n + 255) / 256, 256>>>(Wq, Wk, Wv);              // #2
    }
    {
        int n = L_ * D_ * D_;
        conv_split_kernel<<<(n + 255) / 256, 256>>>(Wo, wo_h, wo_l, n);          // #3
    }
    gemm_pipe<4, 2><<<dim3(1152 / BN, GY4), blk, SMEM_MT4>>>(                    // #4 (profiled)
        xh, xl, wqkv_h, wqkv_l, nullptr, qkv, nullptr, nullptr,
        BT_, 3 * D_, 3 * D_, D_, 0);
    {
        int n = L_ * D_ * FF_;
        conv_split_kernel<<<(n + 255) / 256, 256>>>(W1, w1_h, w1_l, n);          // #5
        conv_split_kernel<<<(n + 255) / 256, 256>>>(W2, w2_h, w2_l, n);          // #6
    }

    for (int l = 0; l < L_; l++) {
        if (l > 0) {
            gemm_pipe<4, 2><<<dim3(1152 / BN, GY4), blk, SMEM_MT4>>>(
                xh, xl, wqkv_h + (size_t)l * D_ * 3 * D_, wqkv_l + (size_t)l * D_ * 3 * D_,
                nullptr, qkv, nullptr, nullptr, BT_, 3 * D_, 3 * D_, D_, 0);
        }
        attn2_kernel<<<B_ * H_, 256, ATTN_SMEM_BYTES>>>();
        gemm_pipe<2, 3><<<dim3(D_ / BN, GY2), blk, SMEM_MT2>>>(
            oh, ol, wo_h + (size_t)l * D_ * D_, wo_l + (size_t)l * D_ * D_,
            bo + (size_t)l * D_, y, nullptr, nullptr, BT_, D_, D_, D_, 0);
        add_ln_kernel<<<BT_, 128>>>(x, y, ln1_g + (size_t)l * D_, ln1_b + (size_t)l * D_, x, 1);
        gemm_pipe<4, 2><<<dim3(FF_ / BN, GY4), blk, SMEM_MT4>>>(
            xh, xl, w1_h + (size_t)l * D_ * FF_, w1_l + (size_t)l * D_ * FF_,
            b1 + (size_t)l * FF_, nullptr, hh, hl, BT_, FF_, FF_, D_, 1);
        gemm_pipe<2, 3><<<dim3(D_ / BN, GY2), blk, SMEM_MT2>>>(
            hh, hl, w2_h + (size_t)l * FF_ * D_, w2_l + (size_t)l * FF_ * D_,
            b2 + (size_t)l * D_, y, nullptr, nullptr, BT_, D_, D_, FF_, 0);
        add_ln_kernel<<<BT_, 128>>>(x, y, ln2_g + (size_t)l * D_, ln2_b + (size_t)l * D_, x, 1);
    }

    add_ln_kernel<<<BT_, 128>>>(x, nullptr, lnf_g, lnf_b, nullptr, 1);

    {
        int n = D_ * VP_;
        conv_wout_kernel<<<(n + 255) / 256, 256>>>(Wout);
    }

    const long long LOGITS = (long long)BT_ * V_;
    if ((long long)out_size >= LOGITS) {
        gemm_pipe<4, 2><<<dim3(VP_ / BN, GY4), blk, SMEM_MT4>>>(
            xh, xl, wout_h, wout_l, bout, out, nullptr, nullptr, BT_, V_, VP_, D_, 0);
        if ((long long)out_size > LOGITS) {
            row_loss_kernel<<<BT_, 256>>>(out, targets);
            reduce_loss_kernel<<<1, 256>>>(out + LOGITS);
        }
    } else {
        loss_direct_kernel<<<Wout ? BT_ : BT_, 256>>>(Wout, bout, targets);
        reduce_loss_kernel<<<1, 256>>>(out);
    }
}